// round 10
// baseline (speedup 1.0000x reference)
#include <cuda_runtime.h>
#include <cuda_bf16.h>
#include <cstdint>

#define TOKENS 4096
#define DMODEL 1024
#define NHEADS 16
#define SEQ 2048

// Persistent split-bf16 copies (hi/lo).
__device__ __align__(16) __nv_bfloat16 g_Xh[TOKENS * DMODEL];
__device__ __align__(16) __nv_bfloat16 g_Xl[TOKENS * DMODEL];
__device__ __align__(16) __nv_bfloat16 g_Wqh[DMODEL * DMODEL];
__device__ __align__(16) __nv_bfloat16 g_Wql[DMODEL * DMODEL];
__device__ __align__(16) __nv_bfloat16 g_Wkh[DMODEL * DMODEL];
__device__ __align__(16) __nv_bfloat16 g_Wkl[DMODEL * DMODEL];
__device__ __align__(16) __nv_bfloat16 g_Wvh[DMODEL * DMODEL];
__device__ __align__(16) __nv_bfloat16 g_Wvl[DMODEL * DMODEL];
__device__ __align__(16) __nv_bfloat16 g_Woh[DMODEL * DMODEL];
__device__ __align__(16) __nv_bfloat16 g_Wol[DMODEL * DMODEL];
// Q (pre-scaled) and K: [B*H][S][64]. V: TRANSPOSED [B*H][64][S]. O: [token][dmodel].
__device__ __align__(16) __nv_bfloat16 g_Qh[TOKENS * DMODEL];
__device__ __align__(16) __nv_bfloat16 g_Ql[TOKENS * DMODEL];
__device__ __align__(16) __nv_bfloat16 g_Kh[TOKENS * DMODEL];
__device__ __align__(16) __nv_bfloat16 g_Kl[TOKENS * DMODEL];
__device__ __align__(16) __nv_bfloat16 g_Vh[TOKENS * DMODEL];
__device__ __align__(16) __nv_bfloat16 g_Vl[TOKENS * DMODEL];
__device__ __align__(16) __nv_bfloat16 g_Oh[TOKENS * DMODEL];
__device__ __align__(16) __nv_bfloat16 g_Ol[TOKENS * DMODEL];

__device__ __forceinline__ float neg_inf() { return __int_as_float(0xff800000u); }

__device__ __forceinline__ uint32_t smem_u32(const void* p) {
    uint32_t a;
    asm("{ .reg .u64 t; cvta.to.shared.u64 t, %1; cvt.u32.u64 %0, t; }"
        : "=r"(a) : "l"(p));
    return a;
}

__device__ __forceinline__ uint32_t pack_bf2(__nv_bfloat16 a, __nv_bfloat16 b) {
    return (uint32_t)__bfloat16_as_ushort(a) |
           ((uint32_t)__bfloat16_as_ushort(b) << 16);
}

__device__ __forceinline__ void split_pack(float a, float b,
                                           uint32_t& h, uint32_t& l) {
    __nv_bfloat16 ha = __float2bfloat16_rn(a);
    __nv_bfloat16 hb = __float2bfloat16_rn(b);
    __nv_bfloat16 la = __float2bfloat16_rn(a - __bfloat162float(ha));
    __nv_bfloat16 lb = __float2bfloat16_rn(b - __bfloat162float(hb));
    h = pack_bf2(ha, hb);
    l = pack_bf2(la, lb);
}

__device__ __forceinline__ void ldsm_x4(uint32_t* r, uint32_t addr) {
    asm volatile("ldmatrix.sync.aligned.m8n8.x4.shared.b16 {%0,%1,%2,%3}, [%4];"
                 : "=r"(r[0]), "=r"(r[1]), "=r"(r[2]), "=r"(r[3]) : "r"(addr));
}

__device__ __forceinline__ void mma16816(float* d, const uint32_t* a,
                                         const uint32_t* b) {
    asm volatile("mma.sync.aligned.m16n8k16.row.col.f32.bf16.bf16.f32 "
                 "{%0,%1,%2,%3}, {%4,%5,%6,%7}, {%8,%9}, {%0,%1,%2,%3};"
                 : "+f"(d[0]), "+f"(d[1]), "+f"(d[2]), "+f"(d[3])
                 : "r"(a[0]), "r"(a[1]), "r"(a[2]), "r"(a[3]),
                   "r"(b[0]), "r"(b[1]));
}

__device__ __forceinline__ void cp16(uint32_t saddr, const void* gaddr) {
    asm volatile("cp.async.cg.shared.global [%0], [%1], 16;"
                 :: "r"(saddr), "l"(gaddr));
}

__device__ __forceinline__ void cp_commit() {
    asm volatile("cp.async.commit_group;" ::: "memory");
}
__device__ __forceinline__ void cp_wait1() {
    asm volatile("cp.async.wait_group 1;" ::: "memory");
}
__device__ __forceinline__ void cp_wait0() {
    asm volatile("cp.async.wait_group 0;" ::: "memory");
}

// ---------------------------------------------------------------------------
// Pre-pass: split fp32 sources into bf16 hi/lo.
// ---------------------------------------------------------------------------

__global__ void convert_split(const float* __restrict__ x,
                              const float* __restrict__ Wq,
                              const float* __restrict__ Wk,
                              const float* __restrict__ Wv,
                              const float* __restrict__ Wo)
{
    const float* src;
    __nv_bfloat16 *dh, *dl;
    int n;
    switch (blockIdx.y) {
        case 0: src = x;  dh = g_Xh;  dl = g_Xl;  n = TOKENS * DMODEL; break;
        case 1: src = Wq; dh = g_Wqh; dl = g_Wql; n = DMODEL * DMODEL; break;
        case 2: src = Wk; dh = g_Wkh; dl = g_Wkl; n = DMODEL * DMODEL; break;
        case 3: src = Wv; dh = g_Wvh; dl = g_Wvl; n = DMODEL * DMODEL; break;
        default: src = Wo; dh = g_Woh; dl = g_Wol; n = DMODEL * DMODEL; break;
    }
    int i = (blockIdx.x * blockDim.x + threadIdx.x) * 4;
    if (i >= n) return;
    float4 v = *(const float4*)(src + i);
    uint32_t h0, h1, l0, l1;
    split_pack(v.x, v.y, h0, l0);
    split_pack(v.z, v.w, h1, l1);
    *(uint2*)(dh + i) = make_uint2(h0, h1);
    *(uint2*)(dl + i) = make_uint2(l0, l1);
}

// ---------------------------------------------------------------------------
// Split-bf16 HMMA GEMM, cp.async 3-stage pipelined, CTA 128x256, BK=32.
// (unchanged from round 9 — at its smem-bandwidth limit)
// ---------------------------------------------------------------------------

__device__ __forceinline__ uint32_t tile_off(int r, int c) {
    return (uint32_t)((r >> 1) * 128 + (((((r & 1) << 2) | c) ^ ((r >> 1) & 7)) << 4));
}

#define G_STAGE 49152
#define GEMM_SMEM_BYTES (3 * G_STAGE)

__global__ __launch_bounds__(256, 1) void gemm_bf16(float* __restrict__ Cout,
                                                    int qkv_mode)
{
    extern __shared__ char sm[];
    const uint32_t sb = smem_u32(sm);
    const int tid = threadIdx.x;
    const int lane = tid & 31;
    const int wid = tid >> 5;
    const int warp_m = wid >> 2;
    const int warp_n = wid & 3;
    const int z = blockIdx.z;

    const __nv_bfloat16 *Ah, *Al, *Bh, *Bl;
    if (qkv_mode) {
        Ah = g_Xh; Al = g_Xl;
        Bh = (z == 0) ? g_Wqh : (z == 1 ? g_Wkh : g_Wvh);
        Bl = (z == 0) ? g_Wql : (z == 1 ? g_Wkl : g_Wvl);
    } else {
        Ah = g_Oh; Al = g_Ol; Bh = g_Woh; Bl = g_Wol;
    }
    const int m0 = blockIdx.y * 128;
    const int n0 = blockIdx.x * 256;
    const __nv_bfloat16* Agh = Ah + (size_t)m0 * DMODEL;
    const __nv_bfloat16* Agl = Al + (size_t)m0 * DMODEL;
    const __nv_bfloat16* Bgh = Bh + (size_t)n0 * DMODEL;
    const __nv_bfloat16* Bgl = Bl + (size_t)n0 * DMODEL;

    const int cA = tid & 3;
    int rA[2]; uint32_t oA[2];
#pragma unroll
    for (int u = 0; u < 2; u++) { rA[u] = (u * 256 + tid) >> 2; oA[u] = tile_off(rA[u], cA); }
    int rB[4]; uint32_t oB[4];
#pragma unroll
    for (int u = 0; u < 4; u++) { rB[u] = (u * 256 + tid) >> 2; oB[u] = tile_off(rB[u], cA); }

    float acc[4][8][4];
#pragma unroll
    for (int i = 0; i < 4; i++)
#pragma unroll
        for (int j = 0; j < 8; j++)
#pragma unroll
            for (int u = 0; u < 4; u++) acc[i][j][u] = 0.f;

    const int a_mat = lane >> 3;
    const int a_khalf = a_mat >> 1;
    int rowA[4];
#pragma unroll
    for (int im = 0; im < 4; im++)
        rowA[im] = warp_m * 64 + im * 16 + (a_mat & 1) * 8 + (lane & 7);
    const int b_row4 = ((lane >> 4) << 3) + (lane & 7);
    const int b_chunk4 = (lane >> 3) & 1;

#define ISSUE(chv)                                                                 \
    do {                                                                           \
        const int _k0 = (chv) * 32;                                                \
        const uint32_t _bs = sb + (uint32_t)(((chv) % 3) * G_STAGE);               \
        cp16(_bs + oA[0],         Agh + (size_t)rA[0] * DMODEL + _k0 + cA * 8);    \
        cp16(_bs + oA[1],         Agh + (size_t)rA[1] * DMODEL + _k0 + cA * 8);    \
        cp16(_bs + 8192 + oA[0],  Agl + (size_t)rA[0] * DMODEL + _k0 + cA * 8);    \
        cp16(_bs + 8192 + oA[1],  Agl + (size_t)rA[1] * DMODEL + _k0 + cA * 8);    \
        cp16(_bs + 16384 + oB[0], Bgh + (size_t)rB[0] * DMODEL + _k0 + cA * 8);    \
        cp16(_bs + 16384 + oB[1], Bgh + (size_t)rB[1] * DMODEL + _k0 + cA * 8);    \
        cp16(_bs + 16384 + oB[2], Bgh + (size_t)rB[2] * DMODEL + _k0 + cA * 8);    \
        cp16(_bs + 16384 + oB[3], Bgh + (size_t)rB[3] * DMODEL + _k0 + cA * 8);    \
        cp16(_bs + 32768 + oB[0], Bgl + (size_t)rB[0] * DMODEL + _k0 + cA * 8);    \
        cp16(_bs + 32768 + oB[1], Bgl + (size_t)rB[1] * DMODEL + _k0 + cA * 8);    \
        cp16(_bs + 32768 + oB[2], Bgl + (size_t)rB[2] * DMODEL + _k0 + cA * 8);    \
        cp16(_bs + 32768 + oB[3], Bgl + (size_t)rB[3] * DMODEL + _k0 + cA * 8);    \
        cp_commit();                                                               \
    } while (0)

    ISSUE(0);
    ISSUE(1);

    for (int ch = 0; ch < 32; ch++) {
        if (ch + 1 < 32) cp_wait1(); else cp_wait0();
        __syncthreads();
        if (ch + 2 < 32) ISSUE(ch + 2);

        const uint32_t bs = sb + (uint32_t)((ch % 3) * G_STAGE);
        const uint32_t sAh = bs, sAl = bs + 8192;
        const uint32_t sBh = bs + 16384, sBl = bs + 32768;
#pragma unroll
        for (int kk = 0; kk < 2; kk++) {
            uint32_t ah[4][4], al[4][4];
#pragma unroll
            for (int im = 0; im < 4; im++) {
                uint32_t off = tile_off(rowA[im], kk * 2 + a_khalf);
                ldsm_x4(ah[im], sAh + off);
                ldsm_x4(al[im], sAl + off);
            }
#pragma unroll
            for (int inp = 0; inp < 4; inp++) {
                uint32_t bh4[4], bl4[4];
                uint32_t off = tile_off(warp_n * 64 + inp * 16 + b_row4,
                                        kk * 2 + b_chunk4);
                ldsm_x4(bh4, sBh + off);
                ldsm_x4(bl4, sBl + off);
#pragma unroll
                for (int im = 0; im < 4; im++) {
                    mma16816(acc[im][2 * inp], ah[im], bh4);
                    mma16816(acc[im][2 * inp], ah[im], bl4);
                    mma16816(acc[im][2 * inp], al[im], bh4);
                    mma16816(acc[im][2 * inp + 1], ah[im], bh4 + 2);
                    mma16816(acc[im][2 * inp + 1], ah[im], bl4 + 2);
                    mma16816(acc[im][2 * inp + 1], al[im], bh4 + 2);
                }
            }
        }
        __syncthreads();
    }
#undef ISSUE

    const int gid = lane >> 2;
    const int tig = lane & 3;
    if (qkv_mode) {
        if (z < 2) {
            __nv_bfloat16* Ch = (z == 0) ? g_Qh : g_Kh;
            __nv_bfloat16* Cl = (z == 0) ? g_Ql : g_Kl;
            const float scale = (z == 0) ? 0.125f : 1.0f;
#pragma unroll
            for (int im = 0; im < 4; im++) {
#pragma unroll
                for (int in = 0; in < 8; in++) {
                    int row = m0 + warp_m * 64 + im * 16 + gid;
                    int col = n0 + warp_n * 64 + in * 8 + tig * 2;
                    int h = col >> 6, hd = col & 63;
#pragma unroll
                    for (int half = 0; half < 2; half++) {
                        int rr = row + half * 8;
                        int bb = rr >> 11, s = rr & 2047;
                        size_t off = (((size_t)(bb * NHEADS + h) * SEQ + s) << 6) + hd;
                        uint32_t hh, ll;
                        split_pack(acc[im][in][half * 2] * scale,
                                   acc[im][in][half * 2 + 1] * scale, hh, ll);
                        *(uint32_t*)(Ch + off) = hh;
                        *(uint32_t*)(Cl + off) = ll;
                    }
                }
            }
        } else {
            // V: write TRANSPOSED [bh][d][s].
#pragma unroll
            for (int im = 0; im < 4; im++) {
#pragma unroll
                for (int in = 0; in < 8; in++) {
                    int row = m0 + warp_m * 64 + im * 16 + gid;
                    int col = n0 + warp_n * 64 + in * 8 + tig * 2;
                    int h = col >> 6, hd = col & 63;
#pragma unroll
                    for (int half = 0; half < 2; half++) {
                        int rr = row + half * 8;
                        int bb = rr >> 11, s = rr & 2047;
                        size_t base = ((size_t)(bb * NHEADS + h) * 64 + hd) * SEQ + s;
#pragma unroll
                        for (int e = 0; e < 2; e++) {
                            float v = acc[im][in][half * 2 + e];
                            __nv_bfloat16 hb = __float2bfloat16_rn(v);
                            __nv_bfloat16 lb =
                                __float2bfloat16_rn(v - __bfloat162float(hb));
                            g_Vh[base + (size_t)e * SEQ] = hb;
                            g_Vl[base + (size_t)e * SEQ] = lb;
                        }
                    }
                }
            }
        }
    } else {
#pragma unroll
        for (int im = 0; im < 4; im++) {
#pragma unroll
            for (int in = 0; in < 8; in++) {
                int row = m0 + warp_m * 64 + im * 16 + gid;
                int col = n0 + warp_n * 64 + in * 8 + tig * 2;
#pragma unroll
                for (int half = 0; half < 2; half++) {
                    int rr = row + half * 8;
                    float* dst = Cout + (size_t)rr * DMODEL + col;
                    dst[0] = acc[im][in][half * 2 + 0];
                    dst[1] = acc[im][in][half * 2 + 1];
                }
            }
        }
    }
}

// ---------------------------------------------------------------------------
// Flash attention (causal), split-bf16 HMMA. Br=256, Bc=64, 8 warps.
// Warp tile 32x64 (2 m-subtiles) -> 2x MMAs per K/V smem byte vs Br=128.
// Smem: Q 64KB (once) | 3 stages x 32KB = 160KB dynamic. Longest CTAs first.
// ---------------------------------------------------------------------------

__device__ __forceinline__ uint32_t fl_off(int r, int c) {
    return (uint32_t)(r * 128 + ((c ^ (r & 7)) << 4));
}

#define F_SMEM_BYTES (65536 + 3 * 32768)

__global__ __launch_bounds__(256, 1) void flash_mma()
{
    extern __shared__ char sm[];
    const uint32_t sb = smem_u32(sm);
    const int tid = threadIdx.x;
    const int lane = tid & 31;
    const int wq = tid >> 5;                      // warp: q-rows wq*32..+31
    const int qt = gridDim.x - 1 - blockIdx.x;    // longest first
    const int bh = blockIdx.y;
    const int q0 = qt * 256;
    const int T = 4 * (qt + 1);

    const __nv_bfloat16* qbh = g_Qh + (size_t)(bh * SEQ + q0) * 64;
    const __nv_bfloat16* qbl = g_Ql + (size_t)(bh * SEQ + q0) * 64;
    const __nv_bfloat16* kbh = g_Kh + (size_t)bh * SEQ * 64;
    const __nv_bfloat16* kbl = g_Kl + (size_t)bh * SEQ * 64;
    const __nv_bfloat16* vth = g_Vh + (size_t)bh * 64 * SEQ;
    const __nv_bfloat16* vtl = g_Vl + (size_t)bh * 64 * SEQ;

    const uint32_t aQh = sb, aQl = sb + 32768;

    // ---- Fill Q once: 256 rows x 8 chunks per array, 8/thread ----
#pragma unroll
    for (int u = 0; u < 8; u++) {
        int lin = u * 256 + tid;
        int r = lin >> 3, c = lin & 7;
        uint32_t off = fl_off(r, c);
        *(uint4*)(sm + off)         = *(const uint4*)(qbh + r * 64 + c * 8);
        *(uint4*)(sm + 32768 + off) = *(const uint4*)(qbl + r * 64 + c * 8);
    }

    int rF[2]; uint32_t oF[2];
#pragma unroll
    for (int u = 0; u < 2; u++) {
        int lin = u * 256 + tid;
        rF[u] = lin >> 3;
        oF[u] = fl_off(rF[u], lin & 7);
    }
    const int cF0 = (tid & 7) * 8, cF1 = ((256 + tid) & 7) * 8;

#define F_ISSUE(tt)                                                                 \
    do {                                                                            \
        const uint32_t _bs = sb + 65536u + (uint32_t)(((tt) % 3) * 32768);          \
        cp16(_bs + oF[0],         kbh + (size_t)((tt) * 64 + rF[0]) * 64 + cF0);    \
        cp16(_bs + oF[1],         kbh + (size_t)((tt) * 64 + rF[1]) * 64 + cF1);    \
        cp16(_bs + 8192 + oF[0],  kbl + (size_t)((tt) * 64 + rF[0]) * 64 + cF0);    \
        cp16(_bs + 8192 + oF[1],  kbl + (size_t)((tt) * 64 + rF[1]) * 64 + cF1);    \
        cp16(_bs + 16384 + oF[0], vth + (size_t)rF[0] * SEQ + (tt) * 64 + cF0);     \
        cp16(_bs + 16384 + oF[1], vth + (size_t)rF[1] * SEQ + (tt) * 64 + cF1);     \
        cp16(_bs + 24576 + oF[0], vtl + (size_t)rF[0] * SEQ + (tt) * 64 + cF0);     \
        cp16(_bs + 24576 + oF[1], vtl + (size_t)rF[1] * SEQ + (tt) * 64 + cF1);     \
        cp_commit();                                                                \
    } while (0)

    F_ISSUE(0);
    F_ISSUE(1);   // T >= 4 always

    const int a_mat = lane >> 3;
    const int a_khalf = a_mat >> 1;
    const int a_row = (a_mat & 1) * 8 + (lane & 7);   // + wq*32 + im*16
    const int b_row4 = ((lane >> 4) << 3) + (lane & 7);
    const int b_chunk4 = (lane >> 3) & 1;
    const int gid = lane >> 2;
    const int tig = lane & 3;

    float m[4], l[4], o[2][8][4], s[2][8][4];
#pragma unroll
    for (int i = 0; i < 4; i++) { m[i] = neg_inf(); l[i] = 0.f; }
#pragma unroll
    for (int im = 0; im < 2; im++)
#pragma unroll
        for (int j = 0; j < 8; j++)
#pragma unroll
            for (int u = 0; u < 4; u++) o[im][j][u] = 0.f;

    for (int t = 0; t < T; t++) {
        if (t + 1 < T) cp_wait1(); else cp_wait0();
        __syncthreads();
        if (t + 2 < T) F_ISSUE(t + 2);

        const uint32_t bs = sb + 65536u + (uint32_t)((t % 3) * 32768);
        const uint32_t aKh = bs, aKl = bs + 8192;
        const uint32_t aVh = bs + 16384, aVl = bs + 24576;

        // ---- S = Q K^T ----
#pragma unroll
        for (int im = 0; im < 2; im++)
#pragma unroll
            for (int j = 0; j < 8; j++)
#pragma unroll
                for (int u = 0; u < 4; u++) s[im][j][u] = 0.f;

#pragma unroll
        for (int kk = 0; kk < 4; kk++) {
            uint32_t ah[2][4], al[2][4];
#pragma unroll
            for (int im = 0; im < 2; im++) {
                uint32_t offa = fl_off(wq * 32 + im * 16 + a_row, kk * 2 + a_khalf);
                ldsm_x4(ah[im], aQh + offa);
                ldsm_x4(al[im], aQl + offa);
            }
#pragma unroll
            for (int jp = 0; jp < 4; jp++) {
                uint32_t bh4[4], bl4[4];
                uint32_t offb = fl_off(jp * 16 + b_row4, kk * 2 + b_chunk4);
                ldsm_x4(bh4, aKh + offb);
                ldsm_x4(bl4, aKl + offb);
#pragma unroll
                for (int im = 0; im < 2; im++) {
                    mma16816(s[im][2 * jp], ah[im], bh4);
                    mma16816(s[im][2 * jp], ah[im], bl4);
                    mma16816(s[im][2 * jp], al[im], bh4);
                    mma16816(s[im][2 * jp + 1], ah[im], bh4 + 2);
                    mma16816(s[im][2 * jp + 1], ah[im], bl4 + 2);
                    mma16816(s[im][2 * jp + 1], al[im], bh4 + 2);
                }
            }
        }

        // ---- Causal mask (last 4 chunks only) ----
        if (t >= 4 * qt) {
#pragma unroll
            for (int im = 0; im < 2; im++) {
#pragma unroll
                for (int j = 0; j < 8; j++) {
#pragma unroll
                    for (int u = 0; u < 4; u++) {
                        int row = q0 + wq * 32 + im * 16 + (u >> 1) * 8 + gid;
                        int col = t * 64 + j * 8 + tig * 2 + (u & 1);
                        if (col > row) s[im][j][u] = neg_inf();
                    }
                }
            }
        }

        // ---- Online softmax: 4 row-groups (im, i) ----
#pragma unroll
        for (int im = 0; im < 2; im++) {
#pragma unroll
            for (int i = 0; i < 2; i++) {
                const int rg = im * 2 + i;
                float mx = neg_inf();
#pragma unroll
                for (int j = 0; j < 8; j++) {
                    mx = fmaxf(mx, s[im][j][i * 2]);
                    mx = fmaxf(mx, s[im][j][i * 2 + 1]);
                }
                mx = fmaxf(mx, __shfl_xor_sync(0xffffffffu, mx, 1));
                mx = fmaxf(mx, __shfl_xor_sync(0xffffffffu, mx, 2));
                float mnew = fmaxf(m[rg], mx);
                float corr = __expf(m[rg] - mnew);
                float rs = 0.f;
#pragma unroll
                for (int j = 0; j < 8; j++) {
                    float e0 = __expf(s[im][j][i * 2] - mnew);
                    float e1 = __expf(s[im][j][i * 2 + 1] - mnew);
                    s[im][j][i * 2] = e0;
                    s[im][j][i * 2 + 1] = e1;
                    rs += e0 + e1;
                }
                rs += __shfl_xor_sync(0xffffffffu, rs, 1);
                rs += __shfl_xor_sync(0xffffffffu, rs, 2);
                l[rg] = l[rg] * corr + rs;
                m[rg] = mnew;
#pragma unroll
                for (int j = 0; j < 8; j++) {
                    o[im][j][i * 2] *= corr;
                    o[im][j][i * 2 + 1] *= corr;
                }
            }
        }

        // ---- O += P Vt ----
#pragma unroll
        for (int kk = 0; kk < 4; kk++) {
            uint32_t ph[2][4], pl[2][4];
#pragma unroll
            for (int im = 0; im < 2; im++) {
#pragma unroll
                for (int half = 0; half < 2; half++) {
                    const float* sv = s[im][2 * kk + half];
                    split_pack(sv[0], sv[1], ph[im][half * 2], pl[im][half * 2]);
                    split_pack(sv[2], sv[3], ph[im][half * 2 + 1], pl[im][half * 2 + 1]);
                }
            }
#pragma unroll
            for (int jp = 0; jp < 4; jp++) {
                uint32_t vh4[4], vl4[4];
                uint32_t offv = fl_off(jp * 16 + b_row4, kk * 2 + b_chunk4);
                ldsm_x4(vh4, aVh + offv);
                ldsm_x4(vl4, aVl + offv);
#pragma unroll
                for (int im = 0; im < 2; im++) {
                    mma16816(o[im][2 * jp], ph[im], vh4);
                    mma16816(o[im][2 * jp], ph[im], vl4);
                    mma16816(o[im][2 * jp], pl[im], vh4);
                    mma16816(o[im][2 * jp + 1], ph[im], vh4 + 2);
                    mma16816(o[im][2 * jp + 1], ph[im], vl4 + 2);
                    mma16816(o[im][2 * jp + 1], pl[im], vh4 + 2);
                }
            }
        }
    }
#undef F_ISSUE

    // ---- Epilogue: normalize, write split-bf16 O [token][dmodel] ----
    const int bb = bh >> 4;
    const int h = bh & 15;
#pragma unroll
    for (int im = 0; im < 2; im++) {
        float inv0 = 1.f / l[im * 2 + 0];
        float inv1 = 1.f / l[im * 2 + 1];
#pragma unroll
        for (int j = 0; j < 8; j++) {
            int col = h * 64 + j * 8 + tig * 2;
            int r0 = q0 + wq * 32 + im * 16 + gid;
            size_t off0 = (size_t)(bb * SEQ + r0) * DMODEL + col;
            size_t off1 = (size_t)(bb * SEQ + r0 + 8) * DMODEL + col;
            uint32_t hh, ll;
            split_pack(o[im][j][0] * inv0, o[im][j][1] * inv0, hh, ll);
            *(uint32_t*)(g_Oh + off0) = hh;
            *(uint32_t*)(g_Ol + off0) = ll;
            split_pack(o[im][j][2] * inv1, o[im][j][3] * inv1, hh, ll);
            *(uint32_t*)(g_Oh + off1) = hh;
            *(uint32_t*)(g_Ol + off1) = ll;
        }
    }
}

// ---------------------------------------------------------------------------

extern "C" void kernel_launch(void* const* d_in, const int* in_sizes, int n_in,
                              void* d_out, int out_size)
{
    (void)in_sizes; (void)n_in; (void)out_size;
    const float* x  = (const float*)d_in[0];
    const float* Wq = (const float*)d_in[1];
    const float* Wk = (const float*)d_in[2];
    const float* Wv = (const float*)d_in[3];
    const float* Wo = (const float*)d_in[4];
    float* out = (float*)d_out;

    cudaFuncSetAttribute(gemm_bf16, cudaFuncAttributeMaxDynamicSharedMemorySize,
                         GEMM_SMEM_BYTES);
    cudaFuncSetAttribute(flash_mma, cudaFuncAttributeMaxDynamicSharedMemorySize,
                         F_SMEM_BYTES);

    convert_split<<<dim3(4096, 5), 256>>>(x, Wq, Wk, Wv, Wo);

    dim3 gqkv(DMODEL / 256, TOKENS / 128, 3);   // (4, 32, 3)
    gemm_bf16<<<gqkv, 256, GEMM_SMEM_BYTES>>>(nullptr, 1);

    dim3 gatt(SEQ / 256, 2 * NHEADS);           // (8, 32)
    flash_mma<<<gatt, 256, F_SMEM_BYTES>>>();

    dim3 gout(DMODEL / 256, TOKENS / 128, 1);   // (4, 32)
    gemm_bf16<<<gout, 256, GEMM_SMEM_BYTES>>>(out, 0);
}

// round 11
// speedup vs baseline: 1.0673x; 1.0673x over previous
#include <cuda_runtime.h>
#include <cuda_bf16.h>
#include <cstdint>

#define TOKENS 4096
#define DMODEL 1024
#define NHEADS 16
#define SEQ 2048

// Persistent split-bf16 copies (hi/lo).
__device__ __align__(16) __nv_bfloat16 g_Xh[TOKENS * DMODEL];
__device__ __align__(16) __nv_bfloat16 g_Xl[TOKENS * DMODEL];
__device__ __align__(16) __nv_bfloat16 g_Wqh[DMODEL * DMODEL];
__device__ __align__(16) __nv_bfloat16 g_Wql[DMODEL * DMODEL];
__device__ __align__(16) __nv_bfloat16 g_Wkh[DMODEL * DMODEL];
__device__ __align__(16) __nv_bfloat16 g_Wkl[DMODEL * DMODEL];
__device__ __align__(16) __nv_bfloat16 g_Wvh[DMODEL * DMODEL];
__device__ __align__(16) __nv_bfloat16 g_Wvl[DMODEL * DMODEL];
__device__ __align__(16) __nv_bfloat16 g_Woh[DMODEL * DMODEL];
__device__ __align__(16) __nv_bfloat16 g_Wol[DMODEL * DMODEL];
// Q (pre-scaled) and K: [B*H][S][64]. V: TRANSPOSED [B*H][64][S]. O: [token][dmodel].
__device__ __align__(16) __nv_bfloat16 g_Qh[TOKENS * DMODEL];
__device__ __align__(16) __nv_bfloat16 g_Ql[TOKENS * DMODEL];
__device__ __align__(16) __nv_bfloat16 g_Kh[TOKENS * DMODEL];
__device__ __align__(16) __nv_bfloat16 g_Kl[TOKENS * DMODEL];
__device__ __align__(16) __nv_bfloat16 g_Vh[TOKENS * DMODEL];
__device__ __align__(16) __nv_bfloat16 g_Vl[TOKENS * DMODEL];
__device__ __align__(16) __nv_bfloat16 g_Oh[TOKENS * DMODEL];
__device__ __align__(16) __nv_bfloat16 g_Ol[TOKENS * DMODEL];

__device__ __forceinline__ float neg_inf() { return __int_as_float(0xff800000u); }

__device__ __forceinline__ uint32_t smem_u32(const void* p) {
    uint32_t a;
    asm("{ .reg .u64 t; cvta.to.shared.u64 t, %1; cvt.u32.u64 %0, t; }"
        : "=r"(a) : "l"(p));
    return a;
}

__device__ __forceinline__ uint32_t pack_bf2(__nv_bfloat16 a, __nv_bfloat16 b) {
    return (uint32_t)__bfloat16_as_ushort(a) |
           ((uint32_t)__bfloat16_as_ushort(b) << 16);
}

__device__ __forceinline__ void split_pack(float a, float b,
                                           uint32_t& h, uint32_t& l) {
    __nv_bfloat16 ha = __float2bfloat16_rn(a);
    __nv_bfloat16 hb = __float2bfloat16_rn(b);
    __nv_bfloat16 la = __float2bfloat16_rn(a - __bfloat162float(ha));
    __nv_bfloat16 lb = __float2bfloat16_rn(b - __bfloat162float(hb));
    h = pack_bf2(ha, hb);
    l = pack_bf2(la, lb);
}

__device__ __forceinline__ void ldsm_x4(uint32_t* r, uint32_t addr) {
    asm volatile("ldmatrix.sync.aligned.m8n8.x4.shared.b16 {%0,%1,%2,%3}, [%4];"
                 : "=r"(r[0]), "=r"(r[1]), "=r"(r[2]), "=r"(r[3]) : "r"(addr));
}

__device__ __forceinline__ void mma16816(float* d, const uint32_t* a,
                                         const uint32_t* b) {
    asm volatile("mma.sync.aligned.m16n8k16.row.col.f32.bf16.bf16.f32 "
                 "{%0,%1,%2,%3}, {%4,%5,%6,%7}, {%8,%9}, {%0,%1,%2,%3};"
                 : "+f"(d[0]), "+f"(d[1]), "+f"(d[2]), "+f"(d[3])
                 : "r"(a[0]), "r"(a[1]), "r"(a[2]), "r"(a[3]),
                   "r"(b[0]), "r"(b[1]));
}

__device__ __forceinline__ void cp16(uint32_t saddr, const void* gaddr) {
    asm volatile("cp.async.cg.shared.global [%0], [%1], 16;"
                 :: "r"(saddr), "l"(gaddr));
}

__device__ __forceinline__ void cp_commit() {
    asm volatile("cp.async.commit_group;" ::: "memory");
}
__device__ __forceinline__ void cp_wait1() {
    asm volatile("cp.async.wait_group 1;" ::: "memory");
}
__device__ __forceinline__ void cp_wait0() {
    asm volatile("cp.async.wait_group 0;" ::: "memory");
}

// ---------------------------------------------------------------------------
// Pre-pass: split fp32 sources into bf16 hi/lo.
// ---------------------------------------------------------------------------

__global__ void convert_split(const float* __restrict__ x,
                              const float* __restrict__ Wq,
                              const float* __restrict__ Wk,
                              const float* __restrict__ Wv,
                              const float* __restrict__ Wo)
{
    const float* src;
    __nv_bfloat16 *dh, *dl;
    int n;
    switch (blockIdx.y) {
        case 0: src = x;  dh = g_Xh;  dl = g_Xl;  n = TOKENS * DMODEL; break;
        case 1: src = Wq; dh = g_Wqh; dl = g_Wql; n = DMODEL * DMODEL; break;
        case 2: src = Wk; dh = g_Wkh; dl = g_Wkl; n = DMODEL * DMODEL; break;
        case 3: src = Wv; dh = g_Wvh; dl = g_Wvl; n = DMODEL * DMODEL; break;
        default: src = Wo; dh = g_Woh; dl = g_Wol; n = DMODEL * DMODEL; break;
    }
    int i = (blockIdx.x * blockDim.x + threadIdx.x) * 4;
    if (i >= n) return;
    float4 v = *(const float4*)(src + i);
    uint32_t h0, h1, l0, l1;
    split_pack(v.x, v.y, h0, l0);
    split_pack(v.z, v.w, h1, l1);
    *(uint2*)(dh + i) = make_uint2(h0, h1);
    *(uint2*)(dl + i) = make_uint2(l0, l1);
}

// ---------------------------------------------------------------------------
// Split-bf16 HMMA GEMM, cp.async 3-stage pipelined, CTA 128x256, BK=32.
// (unchanged — at its smem-crossbar limit, 56%)
// ---------------------------------------------------------------------------

__device__ __forceinline__ uint32_t tile_off(int r, int c) {
    return (uint32_t)((r >> 1) * 128 + (((((r & 1) << 2) | c) ^ ((r >> 1) & 7)) << 4));
}

#define G_STAGE 49152
#define GEMM_SMEM_BYTES (3 * G_STAGE)

__global__ __launch_bounds__(256, 1) void gemm_bf16(float* __restrict__ Cout,
                                                    int qkv_mode)
{
    extern __shared__ char sm[];
    const uint32_t sb = smem_u32(sm);
    const int tid = threadIdx.x;
    const int lane = tid & 31;
    const int wid = tid >> 5;
    const int warp_m = wid >> 2;
    const int warp_n = wid & 3;
    const int z = blockIdx.z;

    const __nv_bfloat16 *Ah, *Al, *Bh, *Bl;
    if (qkv_mode) {
        Ah = g_Xh; Al = g_Xl;
        Bh = (z == 0) ? g_Wqh : (z == 1 ? g_Wkh : g_Wvh);
        Bl = (z == 0) ? g_Wql : (z == 1 ? g_Wkl : g_Wvl);
    } else {
        Ah = g_Oh; Al = g_Ol; Bh = g_Woh; Bl = g_Wol;
    }
    const int m0 = blockIdx.y * 128;
    const int n0 = blockIdx.x * 256;
    const __nv_bfloat16* Agh = Ah + (size_t)m0 * DMODEL;
    const __nv_bfloat16* Agl = Al + (size_t)m0 * DMODEL;
    const __nv_bfloat16* Bgh = Bh + (size_t)n0 * DMODEL;
    const __nv_bfloat16* Bgl = Bl + (size_t)n0 * DMODEL;

    const int cA = tid & 3;
    int rA[2]; uint32_t oA[2];
#pragma unroll
    for (int u = 0; u < 2; u++) { rA[u] = (u * 256 + tid) >> 2; oA[u] = tile_off(rA[u], cA); }
    int rB[4]; uint32_t oB[4];
#pragma unroll
    for (int u = 0; u < 4; u++) { rB[u] = (u * 256 + tid) >> 2; oB[u] = tile_off(rB[u], cA); }

    float acc[4][8][4];
#pragma unroll
    for (int i = 0; i < 4; i++)
#pragma unroll
        for (int j = 0; j < 8; j++)
#pragma unroll
            for (int u = 0; u < 4; u++) acc[i][j][u] = 0.f;

    const int a_mat = lane >> 3;
    const int a_khalf = a_mat >> 1;
    int rowA[4];
#pragma unroll
    for (int im = 0; im < 4; im++)
        rowA[im] = warp_m * 64 + im * 16 + (a_mat & 1) * 8 + (lane & 7);
    const int b_row4 = ((lane >> 4) << 3) + (lane & 7);
    const int b_chunk4 = (lane >> 3) & 1;

#define ISSUE(chv)                                                                 \
    do {                                                                           \
        const int _k0 = (chv) * 32;                                                \
        const uint32_t _bs = sb + (uint32_t)(((chv) % 3) * G_STAGE);               \
        cp16(_bs + oA[0],         Agh + (size_t)rA[0] * DMODEL + _k0 + cA * 8);    \
        cp16(_bs + oA[1],         Agh + (size_t)rA[1] * DMODEL + _k0 + cA * 8);    \
        cp16(_bs + 8192 + oA[0],  Agl + (size_t)rA[0] * DMODEL + _k0 + cA * 8);    \
        cp16(_bs + 8192 + oA[1],  Agl + (size_t)rA[1] * DMODEL + _k0 + cA * 8);    \
        cp16(_bs + 16384 + oB[0], Bgh + (size_t)rB[0] * DMODEL + _k0 + cA * 8);    \
        cp16(_bs + 16384 + oB[1], Bgh + (size_t)rB[1] * DMODEL + _k0 + cA * 8);    \
        cp16(_bs + 16384 + oB[2], Bgh + (size_t)rB[2] * DMODEL + _k0 + cA * 8);    \
        cp16(_bs + 16384 + oB[3], Bgh + (size_t)rB[3] * DMODEL + _k0 + cA * 8);    \
        cp16(_bs + 32768 + oB[0], Bgl + (size_t)rB[0] * DMODEL + _k0 + cA * 8);    \
        cp16(_bs + 32768 + oB[1], Bgl + (size_t)rB[1] * DMODEL + _k0 + cA * 8);    \
        cp16(_bs + 32768 + oB[2], Bgl + (size_t)rB[2] * DMODEL + _k0 + cA * 8);    \
        cp16(_bs + 32768 + oB[3], Bgl + (size_t)rB[3] * DMODEL + _k0 + cA * 8);    \
        cp_commit();                                                               \
    } while (0)

    ISSUE(0);
    ISSUE(1);

    for (int ch = 0; ch < 32; ch++) {
        if (ch + 1 < 32) cp_wait1(); else cp_wait0();
        __syncthreads();
        if (ch + 2 < 32) ISSUE(ch + 2);

        const uint32_t bs = sb + (uint32_t)((ch % 3) * G_STAGE);
        const uint32_t sAh = bs, sAl = bs + 8192;
        const uint32_t sBh = bs + 16384, sBl = bs + 32768;
#pragma unroll
        for (int kk = 0; kk < 2; kk++) {
            uint32_t ah[4][4], al[4][4];
#pragma unroll
            for (int im = 0; im < 4; im++) {
                uint32_t off = tile_off(rowA[im], kk * 2 + a_khalf);
                ldsm_x4(ah[im], sAh + off);
                ldsm_x4(al[im], sAl + off);
            }
#pragma unroll
            for (int inp = 0; inp < 4; inp++) {
                uint32_t bh4[4], bl4[4];
                uint32_t off = tile_off(warp_n * 64 + inp * 16 + b_row4,
                                        kk * 2 + b_chunk4);
                ldsm_x4(bh4, sBh + off);
                ldsm_x4(bl4, sBl + off);
#pragma unroll
                for (int im = 0; im < 4; im++) {
                    mma16816(acc[im][2 * inp], ah[im], bh4);
                    mma16816(acc[im][2 * inp], ah[im], bl4);
                    mma16816(acc[im][2 * inp], al[im], bh4);
                    mma16816(acc[im][2 * inp + 1], ah[im], bh4 + 2);
                    mma16816(acc[im][2 * inp + 1], ah[im], bl4 + 2);
                    mma16816(acc[im][2 * inp + 1], al[im], bh4 + 2);
                }
            }
        }
        __syncthreads();
    }
#undef ISSUE

    const int gid = lane >> 2;
    const int tig = lane & 3;
    if (qkv_mode) {
        if (z < 2) {
            __nv_bfloat16* Ch = (z == 0) ? g_Qh : g_Kh;
            __nv_bfloat16* Cl = (z == 0) ? g_Ql : g_Kl;
            const float scale = (z == 0) ? 0.125f : 1.0f;
#pragma unroll
            for (int im = 0; im < 4; im++) {
#pragma unroll
                for (int in = 0; in < 8; in++) {
                    int row = m0 + warp_m * 64 + im * 16 + gid;
                    int col = n0 + warp_n * 64 + in * 8 + tig * 2;
                    int h = col >> 6, hd = col & 63;
#pragma unroll
                    for (int half = 0; half < 2; half++) {
                        int rr = row + half * 8;
                        int bb = rr >> 11, s = rr & 2047;
                        size_t off = (((size_t)(bb * NHEADS + h) * SEQ + s) << 6) + hd;
                        uint32_t hh, ll;
                        split_pack(acc[im][in][half * 2] * scale,
                                   acc[im][in][half * 2 + 1] * scale, hh, ll);
                        *(uint32_t*)(Ch + off) = hh;
                        *(uint32_t*)(Cl + off) = ll;
                    }
                }
            }
        } else {
            // V: write TRANSPOSED [bh][d][s].
#pragma unroll
            for (int im = 0; im < 4; im++) {
#pragma unroll
                for (int in = 0; in < 8; in++) {
                    int row = m0 + warp_m * 64 + im * 16 + gid;
                    int col = n0 + warp_n * 64 + in * 8 + tig * 2;
                    int h = col >> 6, hd = col & 63;
#pragma unroll
                    for (int half = 0; half < 2; half++) {
                        int rr = row + half * 8;
                        int bb = rr >> 11, s = rr & 2047;
                        size_t base = ((size_t)(bb * NHEADS + h) * 64 + hd) * SEQ + s;
#pragma unroll
                        for (int e = 0; e < 2; e++) {
                            float v = acc[im][in][half * 2 + e];
                            __nv_bfloat16 hb = __float2bfloat16_rn(v);
                            __nv_bfloat16 lb =
                                __float2bfloat16_rn(v - __bfloat162float(hb));
                            g_Vh[base + (size_t)e * SEQ] = hb;
                            g_Vl[base + (size_t)e * SEQ] = lb;
                        }
                    }
                }
            }
        }
    } else {
#pragma unroll
        for (int im = 0; im < 4; im++) {
#pragma unroll
            for (int in = 0; in < 8; in++) {
                int row = m0 + warp_m * 64 + im * 16 + gid;
                int col = n0 + warp_n * 64 + in * 8 + tig * 2;
#pragma unroll
                for (int half = 0; half < 2; half++) {
                    int rr = row + half * 8;
                    float* dst = Cout + (size_t)rr * DMODEL + col;
                    dst[0] = acc[im][in][half * 2 + 0];
                    dst[1] = acc[im][in][half * 2 + 1];
                }
            }
        }
    }
}

// ---------------------------------------------------------------------------
// Flash attention (causal), split-bf16 HMMA. Br=128, Bc=64, 8 warps.
// Round-9 structure; Q FRAGMENTS HOISTED TO REGISTERS (loop-invariant).
// Smem: Q 32KB | 3 stages x 32KB = 128KB dynamic. Longest CTAs first.
// ---------------------------------------------------------------------------

__device__ __forceinline__ uint32_t fl_off(int r, int c) {
    return (uint32_t)(r * 128 + ((c ^ (r & 7)) << 4));
}

#define F_SMEM_BYTES (32768 + 3 * 32768)

__global__ __launch_bounds__(256, 1) void flash_mma()
{
    extern __shared__ char sm[];
    const uint32_t sb = smem_u32(sm);
    const int tid = threadIdx.x;
    const int lane = tid & 31;
    const int wq = tid >> 5;
    const int qt = gridDim.x - 1 - blockIdx.x;   // longest first
    const int bh = blockIdx.y;
    const int q0 = qt * 128;
    const int T = 2 * qt + 2;

    const __nv_bfloat16* qbh = g_Qh + (size_t)(bh * SEQ + q0) * 64;
    const __nv_bfloat16* qbl = g_Ql + (size_t)(bh * SEQ + q0) * 64;
    const __nv_bfloat16* kbh = g_Kh + (size_t)bh * SEQ * 64;
    const __nv_bfloat16* kbl = g_Kl + (size_t)bh * SEQ * 64;
    const __nv_bfloat16* vth = g_Vh + (size_t)bh * 64 * SEQ;
    const __nv_bfloat16* vtl = g_Vl + (size_t)bh * 64 * SEQ;

    const uint32_t aQh = sb, aQl = sb + 16384;

#pragma unroll
    for (int u = 0; u < 4; u++) {
        int lin = u * 256 + tid;
        int r = lin >> 3, c = lin & 7;
        uint32_t off = fl_off(r, c);
        *(uint4*)(sm + off)         = *(const uint4*)(qbh + r * 64 + c * 8);
        *(uint4*)(sm + 16384 + off) = *(const uint4*)(qbl + r * 64 + c * 8);
    }

    int rF[2]; uint32_t oF[2];
#pragma unroll
    for (int u = 0; u < 2; u++) {
        int lin = u * 256 + tid;
        rF[u] = lin >> 3;
        oF[u] = fl_off(rF[u], lin & 7);
    }
    const int cF0 = (tid & 7) * 8, cF1 = ((256 + tid) & 7) * 8;

#define F_ISSUE(tt)                                                                 \
    do {                                                                            \
        const uint32_t _bs = sb + 32768u + (uint32_t)(((tt) % 3) * 32768);          \
        cp16(_bs + oF[0],         kbh + (size_t)((tt) * 64 + rF[0]) * 64 + cF0);    \
        cp16(_bs + oF[1],         kbh + (size_t)((tt) * 64 + rF[1]) * 64 + cF1);    \
        cp16(_bs + 8192 + oF[0],  kbl + (size_t)((tt) * 64 + rF[0]) * 64 + cF0);    \
        cp16(_bs + 8192 + oF[1],  kbl + (size_t)((tt) * 64 + rF[1]) * 64 + cF1);    \
        cp16(_bs + 16384 + oF[0], vth + (size_t)rF[0] * SEQ + (tt) * 64 + cF0);     \
        cp16(_bs + 16384 + oF[1], vth + (size_t)rF[1] * SEQ + (tt) * 64 + cF1);     \
        cp16(_bs + 24576 + oF[0], vtl + (size_t)rF[0] * SEQ + (tt) * 64 + cF0);     \
        cp16(_bs + 24576 + oF[1], vtl + (size_t)rF[1] * SEQ + (tt) * 64 + cF1);     \
        cp_commit();                                                                \
    } while (0)

    F_ISSUE(0);
    F_ISSUE(1);   // T >= 2 always

    const int a_mat = lane >> 3;
    const int a_khalf = a_mat >> 1;
    const int rowA = wq * 16 + (a_mat & 1) * 8 + (lane & 7);
    const int b_row4 = ((lane >> 4) << 3) + (lane & 7);
    const int b_chunk4 = (lane >> 3) & 1;
    const int gid = lane >> 2;
    const int tig = lane & 3;

    // ---- Hoist Q fragments (loop-invariant): 32 regs ----
    __syncthreads();   // Q fill visible to all warps
    uint32_t qh[4][4], ql[4][4];
#pragma unroll
    for (int kk = 0; kk < 4; kk++) {
        uint32_t offa = fl_off(rowA, kk * 2 + a_khalf);
        ldsm_x4(qh[kk], aQh + offa);
        ldsm_x4(ql[kk], aQl + offa);
    }

    float m[2], l[2], o[8][4], s[8][4];
#pragma unroll
    for (int i = 0; i < 2; i++) { m[i] = neg_inf(); l[i] = 0.f; }
#pragma unroll
    for (int j = 0; j < 8; j++)
#pragma unroll
        for (int u = 0; u < 4; u++) o[j][u] = 0.f;

    for (int t = 0; t < T; t++) {
        if (t + 1 < T) cp_wait1(); else cp_wait0();
        __syncthreads();
        if (t + 2 < T) F_ISSUE(t + 2);

        const uint32_t bs = sb + 32768u + (uint32_t)((t % 3) * 32768);
        const uint32_t aKh = bs, aKl = bs + 8192;
        const uint32_t aVh = bs + 16384, aVl = bs + 24576;

        // ---- S = Q K^T (Q frags from registers) ----
#pragma unroll
        for (int j = 0; j < 8; j++)
#pragma unroll
            for (int u = 0; u < 4; u++) s[j][u] = 0.f;

#pragma unroll
        for (int kk = 0; kk < 4; kk++) {
#pragma unroll
            for (int jp = 0; jp < 4; jp++) {
                uint32_t bh4[4], bl4[4];
                uint32_t offb = fl_off(jp * 16 + b_row4, kk * 2 + b_chunk4);
                ldsm_x4(bh4, aKh + offb);
                ldsm_x4(bl4, aKl + offb);
                mma16816(s[2 * jp], qh[kk], bh4);
                mma16816(s[2 * jp], qh[kk], bl4);
                mma16816(s[2 * jp], ql[kk], bh4);
                mma16816(s[2 * jp + 1], qh[kk], bh4 + 2);
                mma16816(s[2 * jp + 1], qh[kk], bl4 + 2);
                mma16816(s[2 * jp + 1], ql[kk], bh4 + 2);
            }
        }

        if (t >= 2 * qt) {
#pragma unroll
            for (int j = 0; j < 8; j++) {
#pragma unroll
                for (int u = 0; u < 4; u++) {
                    int row = q0 + wq * 16 + (u >> 1) * 8 + gid;
                    int col = t * 64 + j * 8 + tig * 2 + (u & 1);
                    if (col > row) s[j][u] = neg_inf();
                }
            }
        }

        // ---- Online softmax ----
#pragma unroll
        for (int i = 0; i < 2; i++) {
            float mx = neg_inf();
#pragma unroll
            for (int j = 0; j < 8; j++) {
                mx = fmaxf(mx, s[j][i * 2]);
                mx = fmaxf(mx, s[j][i * 2 + 1]);
            }
            mx = fmaxf(mx, __shfl_xor_sync(0xffffffffu, mx, 1));
            mx = fmaxf(mx, __shfl_xor_sync(0xffffffffu, mx, 2));
            float mnew = fmaxf(m[i], mx);
            float corr = __expf(m[i] - mnew);
            float rs = 0.f;
#pragma unroll
            for (int j = 0; j < 8; j++) {
                float e0 = __expf(s[j][i * 2] - mnew);
                float e1 = __expf(s[j][i * 2 + 1] - mnew);
                s[j][i * 2] = e0;
                s[j][i * 2 + 1] = e1;
                rs += e0 + e1;
            }
            rs += __shfl_xor_sync(0xffffffffu, rs, 1);
            rs += __shfl_xor_sync(0xffffffffu, rs, 2);
            l[i] = l[i] * corr + rs;
            m[i] = mnew;
#pragma unroll
            for (int j = 0; j < 8; j++) {
                o[j][i * 2] *= corr;
                o[j][i * 2 + 1] *= corr;
            }
        }

        // ---- O += P Vt ----
#pragma unroll
        for (int kk = 0; kk < 4; kk++) {
            uint32_t ph[4], pl[4];
#pragma unroll
            for (int half = 0; half < 2; half++) {
                const float* sv = s[2 * kk + half];
                split_pack(sv[0], sv[1], ph[half * 2], pl[half * 2]);
                split_pack(sv[2], sv[3], ph[half * 2 + 1], pl[half * 2 + 1]);
            }
#pragma unroll
            for (int jp = 0; jp < 4; jp++) {
                uint32_t vh4[4], vl4[4];
                uint32_t offv = fl_off(jp * 16 + b_row4, kk * 2 + b_chunk4);
                ldsm_x4(vh4, aVh + offv);
                ldsm_x4(vl4, aVl + offv);
                mma16816(o[2 * jp], ph, vh4);
                mma16816(o[2 * jp], ph, vl4);
                mma16816(o[2 * jp], pl, vh4);
                mma16816(o[2 * jp + 1], ph, vh4 + 2);
                mma16816(o[2 * jp + 1], ph, vl4 + 2);
                mma16816(o[2 * jp + 1], pl, vh4 + 2);
            }
        }
    }
#undef F_ISSUE

    const int bb = bh >> 4;
    const int h = bh & 15;
    float inv0 = 1.f / l[0];
    float inv1 = 1.f / l[1];
#pragma unroll
    for (int j = 0; j < 8; j++) {
        int col = h * 64 + j * 8 + tig * 2;
        int r0 = q0 + wq * 16 + gid;
        size_t off0 = (size_t)(bb * SEQ + r0) * DMODEL + col;
        size_t off1 = (size_t)(bb * SEQ + r0 + 8) * DMODEL + col;
        uint32_t hh, ll;
        split_pack(o[j][0] * inv0, o[j][1] * inv0, hh, ll);
        *(uint32_t*)(g_Oh + off0) = hh;
        *(uint32_t*)(g_Ol + off0) = ll;
        split_pack(o[j][2] * inv1, o[j][3] * inv1, hh, ll);
        *(uint32_t*)(g_Oh + off1) = hh;
        *(uint32_t*)(g_Ol + off1) = ll;
    }
}

// ---------------------------------------------------------------------------

extern "C" void kernel_launch(void* const* d_in, const int* in_sizes, int n_in,
                              void* d_out, int out_size)
{
    (void)in_sizes; (void)n_in; (void)out_size;
    const float* x  = (const float*)d_in[0];
    const float* Wq = (const float*)d_in[1];
    const float* Wk = (const float*)d_in[2];
    const float* Wv = (const float*)d_in[3];
    const float* Wo = (const float*)d_in[4];
    float* out = (float*)d_out;

    cudaFuncSetAttribute(gemm_bf16, cudaFuncAttributeMaxDynamicSharedMemorySize,
                         GEMM_SMEM_BYTES);
    cudaFuncSetAttribute(flash_mma, cudaFuncAttributeMaxDynamicSharedMemorySize,
                         F_SMEM_BYTES);

    convert_split<<<dim3(4096, 5), 256>>>(x, Wq, Wk, Wv, Wo);

    dim3 gqkv(DMODEL / 256, TOKENS / 128, 3);   // (4, 32, 3)
    gemm_bf16<<<gqkv, 256, GEMM_SMEM_BYTES>>>(nullptr, 1);

    dim3 gatt(SEQ / 128, 2 * NHEADS);           // (16, 32)
    flash_mma<<<gatt, 256, F_SMEM_BYTES>>>();

    dim3 gout(DMODEL / 256, TOKENS / 128, 1);   // (4, 32)
    gemm_bf16<<<gout, 256, GEMM_SMEM_BYTES>>>(out, 0);
}

// round 13
// speedup vs baseline: 1.2899x; 1.2086x over previous
#include <cuda_runtime.h>
#include <cuda_bf16.h>
#include <cuda_fp16.h>
#include <cstdint>

#define TOKENS 4096
#define DMODEL 1024
#define NHEADS 16
#define SEQ 2048

// X and O: fp16 split (hi/lo). Weights: plain fp16. Q/K/V: bf16 split (flash unchanged).
__device__ __align__(16) __half g_Xh[TOKENS * DMODEL];
__device__ __align__(16) __half g_Xl[TOKENS * DMODEL];
__device__ __align__(16) __half g_Wq[DMODEL * DMODEL];
__device__ __align__(16) __half g_Wk[DMODEL * DMODEL];
__device__ __align__(16) __half g_Wv[DMODEL * DMODEL];
__device__ __align__(16) __half g_Wo[DMODEL * DMODEL];
// Q (pre-scaled) and K: [B*H][S][64] bf16 hi/lo. V: TRANSPOSED [B*H][64][S] bf16 hi/lo.
__device__ __align__(16) __nv_bfloat16 g_Qh[TOKENS * DMODEL];
__device__ __align__(16) __nv_bfloat16 g_Ql[TOKENS * DMODEL];
__device__ __align__(16) __nv_bfloat16 g_Kh[TOKENS * DMODEL];
__device__ __align__(16) __nv_bfloat16 g_Kl[TOKENS * DMODEL];
__device__ __align__(16) __nv_bfloat16 g_Vh[TOKENS * DMODEL];
__device__ __align__(16) __nv_bfloat16 g_Vl[TOKENS * DMODEL];
// O: fp16 split [token][dmodel].
__device__ __align__(16) __half g_Oh[TOKENS * DMODEL];
__device__ __align__(16) __half g_Ol[TOKENS * DMODEL];

__device__ __forceinline__ float neg_inf() { return __int_as_float(0xff800000u); }

__device__ __forceinline__ uint32_t smem_u32(const void* p) {
    uint32_t a;
    asm("{ .reg .u64 t; cvta.to.shared.u64 t, %1; cvt.u32.u64 %0, t; }"
        : "=r"(a) : "l"(p));
    return a;
}

__device__ __forceinline__ uint32_t pack_bf2(__nv_bfloat16 a, __nv_bfloat16 b) {
    return (uint32_t)__bfloat16_as_ushort(a) |
           ((uint32_t)__bfloat16_as_ushort(b) << 16);
}

__device__ __forceinline__ void split_pack(float a, float b,
                                           uint32_t& h, uint32_t& l) {
    __nv_bfloat16 ha = __float2bfloat16_rn(a);
    __nv_bfloat16 hb = __float2bfloat16_rn(b);
    __nv_bfloat16 la = __float2bfloat16_rn(a - __bfloat162float(ha));
    __nv_bfloat16 lb = __float2bfloat16_rn(b - __bfloat162float(hb));
    h = pack_bf2(ha, hb);
    l = pack_bf2(la, lb);
}

__device__ __forceinline__ uint32_t pack_h2(__half a, __half b) {
    return (uint32_t)__half_as_ushort(a) | ((uint32_t)__half_as_ushort(b) << 16);
}

__device__ __forceinline__ void split_pack_f16(float a, float b,
                                               uint32_t& h, uint32_t& l) {
    __half ha = __float2half_rn(a);
    __half hb = __float2half_rn(b);
    __half la = __float2half_rn(a - __half2float(ha));
    __half lb = __float2half_rn(b - __half2float(hb));
    h = pack_h2(ha, hb);
    l = pack_h2(la, lb);
}

__device__ __forceinline__ void ldsm_x4(uint32_t* r, uint32_t addr) {
    asm volatile("ldmatrix.sync.aligned.m8n8.x4.shared.b16 {%0,%1,%2,%3}, [%4];"
                 : "=r"(r[0]), "=r"(r[1]), "=r"(r[2]), "=r"(r[3]) : "r"(addr));
}

// bf16 variant (flash)
__device__ __forceinline__ void mma16816(float* d, const uint32_t* a,
                                         const uint32_t* b) {
    asm volatile("mma.sync.aligned.m16n8k16.row.col.f32.bf16.bf16.f32 "
                 "{%0,%1,%2,%3}, {%4,%5,%6,%7}, {%8,%9}, {%0,%1,%2,%3};"
                 : "+f"(d[0]), "+f"(d[1]), "+f"(d[2]), "+f"(d[3])
                 : "r"(a[0]), "r"(a[1]), "r"(a[2]), "r"(a[3]),
                   "r"(b[0]), "r"(b[1]));
}

// fp16 variant (GEMMs)
__device__ __forceinline__ void mma16816h(float* d, const uint32_t* a,
                                          const uint32_t* b) {
    asm volatile("mma.sync.aligned.m16n8k16.row.col.f32.f16.f16.f32 "
                 "{%0,%1,%2,%3}, {%4,%5,%6,%7}, {%8,%9}, {%0,%1,%2,%3};"
                 : "+f"(d[0]), "+f"(d[1]), "+f"(d[2]), "+f"(d[3])
                 : "r"(a[0]), "r"(a[1]), "r"(a[2]), "r"(a[3]),
                   "r"(b[0]), "r"(b[1]));
}

__device__ __forceinline__ void cp16(uint32_t saddr, const void* gaddr) {
    asm volatile("cp.async.cg.shared.global [%0], [%1], 16;"
                 :: "r"(saddr), "l"(gaddr));
}

__device__ __forceinline__ void cp_commit() {
    asm volatile("cp.async.commit_group;" ::: "memory");
}
__device__ __forceinline__ void cp_wait1() {
    asm volatile("cp.async.wait_group 1;" ::: "memory");
}
__device__ __forceinline__ void cp_wait0() {
    asm volatile("cp.async.wait_group 0;" ::: "memory");
}

// ---------------------------------------------------------------------------
// Pre-pass: X -> fp16 hi/lo; weights -> plain fp16.
// ---------------------------------------------------------------------------

__global__ void convert_split(const float* __restrict__ x,
                              const float* __restrict__ Wq,
                              const float* __restrict__ Wk,
                              const float* __restrict__ Wv,
                              const float* __restrict__ Wo)
{
    int i = (blockIdx.x * blockDim.x + threadIdx.x) * 4;
    if (blockIdx.y == 0) {
        if (i >= TOKENS * DMODEL) return;
        float4 v = *(const float4*)(x + i);
        uint32_t h0, h1, l0, l1;
        split_pack_f16(v.x, v.y, h0, l0);
        split_pack_f16(v.z, v.w, h1, l1);
        *(uint2*)(g_Xh + i) = make_uint2(h0, h1);
        *(uint2*)(g_Xl + i) = make_uint2(l0, l1);
    } else {
        if (i >= DMODEL * DMODEL) return;
        const float* src = (blockIdx.y == 1) ? Wq :
                           (blockIdx.y == 2) ? Wk :
                           (blockIdx.y == 3) ? Wv : Wo;
        __half* dst = (blockIdx.y == 1) ? g_Wq :
                      (blockIdx.y == 2) ? g_Wk :
                      (blockIdx.y == 3) ? g_Wv : g_Wo;
        float4 v = *(const float4*)(src + i);
        uint32_t h0 = pack_h2(__float2half_rn(v.x), __float2half_rn(v.y));
        uint32_t h1 = pack_h2(__float2half_rn(v.z), __float2half_rn(v.w));
        *(uint2*)(dst + i) = make_uint2(h0, h1);
    }
}

// ---------------------------------------------------------------------------
// fp16 2-MMA HMMA GEMM: A split (h,l), B plain. CTA 128x256, BK=32, 3-stage.
// Stage: Ah 8KB | Al 8KB | Bh 16KB = 32KB.
// ---------------------------------------------------------------------------

__device__ __forceinline__ uint32_t tile_off(int r, int c) {
    return (uint32_t)((r >> 1) * 128 + (((((r & 1) << 2) | c) ^ ((r >> 1) & 7)) << 4));
}

#define G_STAGE 32768
#define GEMM_SMEM_BYTES (3 * G_STAGE)

__global__ __launch_bounds__(256, 1) void gemm_f16(float* __restrict__ Cout,
                                                   int qkv_mode)
{
    extern __shared__ char sm[];
    const uint32_t sb = smem_u32(sm);
    const int tid = threadIdx.x;
    const int lane = tid & 31;
    const int wid = tid >> 5;
    const int warp_m = wid >> 2;
    const int warp_n = wid & 3;
    const int z = blockIdx.z;

    const __half *Ah, *Al, *Bp;
    if (qkv_mode) {
        Ah = g_Xh; Al = g_Xl;
        Bp = (z == 0) ? g_Wq : (z == 1 ? g_Wk : g_Wv);
    } else {
        Ah = g_Oh; Al = g_Ol; Bp = g_Wo;
    }
    const int m0 = blockIdx.y * 128;
    const int n0 = blockIdx.x * 256;
    const __half* Agh = Ah + (size_t)m0 * DMODEL;
    const __half* Agl = Al + (size_t)m0 * DMODEL;
    const __half* Bg  = Bp + (size_t)n0 * DMODEL;

    const int cA = tid & 3;
    int rA[2]; uint32_t oA[2];
#pragma unroll
    for (int u = 0; u < 2; u++) { rA[u] = (u * 256 + tid) >> 2; oA[u] = tile_off(rA[u], cA); }
    int rB[4]; uint32_t oB[4];
#pragma unroll
    for (int u = 0; u < 4; u++) { rB[u] = (u * 256 + tid) >> 2; oB[u] = tile_off(rB[u], cA); }

    float acc[4][8][4];
#pragma unroll
    for (int i = 0; i < 4; i++)
#pragma unroll
        for (int j = 0; j < 8; j++)
#pragma unroll
            for (int u = 0; u < 4; u++) acc[i][j][u] = 0.f;

    const int a_mat = lane >> 3;
    const int a_khalf = a_mat >> 1;
    int rowA[4];
#pragma unroll
    for (int im = 0; im < 4; im++)
        rowA[im] = warp_m * 64 + im * 16 + (a_mat & 1) * 8 + (lane & 7);
    const int b_row4 = ((lane >> 4) << 3) + (lane & 7);
    const int b_chunk4 = (lane >> 3) & 1;

#define ISSUE(chv)                                                                 \
    do {                                                                           \
        const int _k0 = (chv) * 32;                                                \
        const uint32_t _bs = sb + (uint32_t)(((chv) % 3) * G_STAGE);               \
        cp16(_bs + oA[0],         Agh + (size_t)rA[0] * DMODEL + _k0 + cA * 8);    \
        cp16(_bs + oA[1],         Agh + (size_t)rA[1] * DMODEL + _k0 + cA * 8);    \
        cp16(_bs + 8192 + oA[0],  Agl + (size_t)rA[0] * DMODEL + _k0 + cA * 8);    \
        cp16(_bs + 8192 + oA[1],  Agl + (size_t)rA[1] * DMODEL + _k0 + cA * 8);    \
        cp16(_bs + 16384 + oB[0], Bg  + (size_t)rB[0] * DMODEL + _k0 + cA * 8);    \
        cp16(_bs + 16384 + oB[1], Bg  + (size_t)rB[1] * DMODEL + _k0 + cA * 8);    \
        cp16(_bs + 16384 + oB[2], Bg  + (size_t)rB[2] * DMODEL + _k0 + cA * 8);    \
        cp16(_bs + 16384 + oB[3], Bg  + (size_t)rB[3] * DMODEL + _k0 + cA * 8);    \
        cp_commit();                                                               \
    } while (0)

    ISSUE(0);
    ISSUE(1);

    for (int ch = 0; ch < 32; ch++) {
        if (ch + 1 < 32) cp_wait1(); else cp_wait0();
        __syncthreads();
        if (ch + 2 < 32) ISSUE(ch + 2);

        const uint32_t bs = sb + (uint32_t)((ch % 3) * G_STAGE);
        const uint32_t sAh = bs, sAl = bs + 8192;
        const uint32_t sBh = bs + 16384;
#pragma unroll
        for (int kk = 0; kk < 2; kk++) {
            uint32_t ah[4][4], al[4][4];
#pragma unroll
            for (int im = 0; im < 4; im++) {
                uint32_t off = tile_off(rowA[im], kk * 2 + a_khalf);
                ldsm_x4(ah[im], sAh + off);
                ldsm_x4(al[im], sAl + off);
            }
#pragma unroll
            for (int inp = 0; inp < 4; inp++) {
                uint32_t bh4[4];
                uint32_t off = tile_off(warp_n * 64 + inp * 16 + b_row4,
                                        kk * 2 + b_chunk4);
                ldsm_x4(bh4, sBh + off);
#pragma unroll
                for (int im = 0; im < 4; im++) {
                    mma16816h(acc[im][2 * inp], ah[im], bh4);
                    mma16816h(acc[im][2 * inp], al[im], bh4);
                    mma16816h(acc[im][2 * inp + 1], ah[im], bh4 + 2);
                    mma16816h(acc[im][2 * inp + 1], al[im], bh4 + 2);
                }
            }
        }
        __syncthreads();
    }
#undef ISSUE

    const int gid = lane >> 2;
    const int tig = lane & 3;
    if (qkv_mode) {
        if (z < 2) {
            __nv_bfloat16* Ch = (z == 0) ? g_Qh : g_Kh;
            __nv_bfloat16* Cl = (z == 0) ? g_Ql : g_Kl;
            const float scale = (z == 0) ? 0.125f : 1.0f;
#pragma unroll
            for (int im = 0; im < 4; im++) {
#pragma unroll
                for (int in = 0; in < 8; in++) {
                    int row = m0 + warp_m * 64 + im * 16 + gid;
                    int col = n0 + warp_n * 64 + in * 8 + tig * 2;
                    int h = col >> 6, hd = col & 63;
#pragma unroll
                    for (int half = 0; half < 2; half++) {
                        int rr = row + half * 8;
                        int bb = rr >> 11, s = rr & 2047;
                        size_t off = (((size_t)(bb * NHEADS + h) * SEQ + s) << 6) + hd;
                        uint32_t hh, ll;
                        split_pack(acc[im][in][half * 2] * scale,
                                   acc[im][in][half * 2 + 1] * scale, hh, ll);
                        *(uint32_t*)(Ch + off) = hh;
                        *(uint32_t*)(Cl + off) = ll;
                    }
                }
            }
        } else {
            // V: write TRANSPOSED [bh][d][s], bf16 split.
#pragma unroll
            for (int im = 0; im < 4; im++) {
#pragma unroll
                for (int in = 0; in < 8; in++) {
                    int row = m0 + warp_m * 64 + im * 16 + gid;
                    int col = n0 + warp_n * 64 + in * 8 + tig * 2;
                    int h = col >> 6, hd = col & 63;
#pragma unroll
                    for (int half = 0; half < 2; half++) {
                        int rr = row + half * 8;
                        int bb = rr >> 11, s = rr & 2047;
                        size_t base = ((size_t)(bb * NHEADS + h) * 64 + hd) * SEQ + s;
#pragma unroll
                        for (int e = 0; e < 2; e++) {
                            float v = acc[im][in][half * 2 + e];
                            __nv_bfloat16 hb = __float2bfloat16_rn(v);
                            __nv_bfloat16 lb =
                                __float2bfloat16_rn(v - __bfloat162float(hb));
                            g_Vh[base + (size_t)e * SEQ] = hb;
                            g_Vl[base + (size_t)e * SEQ] = lb;
                        }
                    }
                }
            }
        }
    } else {
#pragma unroll
        for (int im = 0; im < 4; im++) {
#pragma unroll
            for (int in = 0; in < 8; in++) {
                int row = m0 + warp_m * 64 + im * 16 + gid;
                int col = n0 + warp_n * 64 + in * 8 + tig * 2;
#pragma unroll
                for (int half = 0; half < 2; half++) {
                    int rr = row + half * 8;
                    float* dst = Cout + (size_t)rr * DMODEL + col;
                    dst[0] = acc[im][in][half * 2 + 0];
                    dst[1] = acc[im][in][half * 2 + 1];
                }
            }
        }
    }
}

// ---------------------------------------------------------------------------
// Flash attention (causal), split-bf16 HMMA. Br=128, Bc=64, 8 warps.
// Unchanged (validated) except O-epilogue writes fp16 hi/lo.
// ---------------------------------------------------------------------------

__device__ __forceinline__ uint32_t fl_off(int r, int c) {
    return (uint32_t)(r * 128 + ((c ^ (r & 7)) << 4));
}

#define F_SMEM_BYTES (32768 + 3 * 32768)

__global__ __launch_bounds__(256, 1) void flash_mma()
{
    extern __shared__ char sm[];
    const uint32_t sb = smem_u32(sm);
    const int tid = threadIdx.x;
    const int lane = tid & 31;
    const int wq = tid >> 5;
    const int qt = gridDim.x - 1 - blockIdx.x;   // longest first
    const int bh = blockIdx.y;
    const int q0 = qt * 128;
    const int T = 2 * qt + 2;

    const __nv_bfloat16* qbh = g_Qh + (size_t)(bh * SEQ + q0) * 64;
    const __nv_bfloat16* qbl = g_Ql + (size_t)(bh * SEQ + q0) * 64;
    const __nv_bfloat16* kbh = g_Kh + (size_t)bh * SEQ * 64;
    const __nv_bfloat16* kbl = g_Kl + (size_t)bh * SEQ * 64;
    const __nv_bfloat16* vth = g_Vh + (size_t)bh * 64 * SEQ;
    const __nv_bfloat16* vtl = g_Vl + (size_t)bh * 64 * SEQ;

    const uint32_t aQh = sb, aQl = sb + 16384;

#pragma unroll
    for (int u = 0; u < 4; u++) {
        int lin = u * 256 + tid;
        int r = lin >> 3, c = lin & 7;
        uint32_t off = fl_off(r, c);
        *(uint4*)(sm + off)         = *(const uint4*)(qbh + r * 64 + c * 8);
        *(uint4*)(sm + 16384 + off) = *(const uint4*)(qbl + r * 64 + c * 8);
    }

    int rF[2]; uint32_t oF[2];
#pragma unroll
    for (int u = 0; u < 2; u++) {
        int lin = u * 256 + tid;
        rF[u] = lin >> 3;
        oF[u] = fl_off(rF[u], lin & 7);
    }
    const int cF0 = (tid & 7) * 8, cF1 = ((256 + tid) & 7) * 8;

#define F_ISSUE(tt)                                                                 \
    do {                                                                            \
        const uint32_t _bs = sb + 32768u + (uint32_t)(((tt) % 3) * 32768);          \
        cp16(_bs + oF[0],         kbh + (size_t)((tt) * 64 + rF[0]) * 64 + cF0);    \
        cp16(_bs + oF[1],         kbh + (size_t)((tt) * 64 + rF[1]) * 64 + cF1);    \
        cp16(_bs + 8192 + oF[0],  kbl + (size_t)((tt) * 64 + rF[0]) * 64 + cF0);    \
        cp16(_bs + 8192 + oF[1],  kbl + (size_t)((tt) * 64 + rF[1]) * 64 + cF1);    \
        cp16(_bs + 16384 + oF[0], vth + (size_t)rF[0] * SEQ + (tt) * 64 + cF0);     \
        cp16(_bs + 16384 + oF[1], vth + (size_t)rF[1] * SEQ + (tt) * 64 + cF1);     \
        cp16(_bs + 24576 + oF[0], vtl + (size_t)rF[0] * SEQ + (tt) * 64 + cF0);     \
        cp16(_bs + 24576 + oF[1], vtl + (size_t)rF[1] * SEQ + (tt) * 64 + cF1);     \
        cp_commit();                                                                \
    } while (0)

    F_ISSUE(0);
    F_ISSUE(1);   // T >= 2 always

    const int a_mat = lane >> 3;
    const int a_khalf = a_mat >> 1;
    const int rowA = wq * 16 + (a_mat & 1) * 8 + (lane & 7);
    const int b_row4 = ((lane >> 4) << 3) + (lane & 7);
    const int b_chunk4 = (lane >> 3) & 1;
    const int gid = lane >> 2;
    const int tig = lane & 3;

    // ---- Hoist Q fragments (loop-invariant) ----
    __syncthreads();
    uint32_t qh[4][4], ql[4][4];
#pragma unroll
    for (int kk = 0; kk < 4; kk++) {
        uint32_t offa = fl_off(rowA, kk * 2 + a_khalf);
        ldsm_x4(qh[kk], aQh + offa);
        ldsm_x4(ql[kk], aQl + offa);
    }

    float m[2], l[2], o[8][4], s[8][4];
#pragma unroll
    for (int i = 0; i < 2; i++) { m[i] = neg_inf(); l[i] = 0.f; }
#pragma unroll
    for (int j = 0; j < 8; j++)
#pragma unroll
        for (int u = 0; u < 4; u++) o[j][u] = 0.f;

    for (int t = 0; t < T; t++) {
        if (t + 1 < T) cp_wait1(); else cp_wait0();
        __syncthreads();
        if (t + 2 < T) F_ISSUE(t + 2);

        const uint32_t bs = sb + 32768u + (uint32_t)((t % 3) * 32768);
        const uint32_t aKh = bs, aKl = bs + 8192;
        const uint32_t aVh = bs + 16384, aVl = bs + 24576;

        // ---- S = Q K^T ----
#pragma unroll
        for (int j = 0; j < 8; j++)
#pragma unroll
            for (int u = 0; u < 4; u++) s[j][u] = 0.f;

#pragma unroll
        for (int kk = 0; kk < 4; kk++) {
#pragma unroll
            for (int jp = 0; jp < 4; jp++) {
                uint32_t bh4[4], bl4[4];
                uint32_t offb = fl_off(jp * 16 + b_row4, kk * 2 + b_chunk4);
                ldsm_x4(bh4, aKh + offb);
                ldsm_x4(bl4, aKl + offb);
                mma16816(s[2 * jp], qh[kk], bh4);
                mma16816(s[2 * jp], qh[kk], bl4);
                mma16816(s[2 * jp], ql[kk], bh4);
                mma16816(s[2 * jp + 1], qh[kk], bh4 + 2);
                mma16816(s[2 * jp + 1], qh[kk], bl4 + 2);
                mma16816(s[2 * jp + 1], ql[kk], bh4 + 2);
            }
        }

        if (t >= 2 * qt) {
#pragma unroll
            for (int j = 0; j < 8; j++) {
#pragma unroll
                for (int u = 0; u < 4; u++) {
                    int row = q0 + wq * 16 + (u >> 1) * 8 + gid;
                    int col = t * 64 + j * 8 + tig * 2 + (u & 1);
                    if (col > row) s[j][u] = neg_inf();
                }
            }
        }

        // ---- Online softmax ----
#pragma unroll
        for (int i = 0; i < 2; i++) {
            float mx = neg_inf();
#pragma unroll
            for (int j = 0; j < 8; j++) {
                mx = fmaxf(mx, s[j][i * 2]);
                mx = fmaxf(mx, s[j][i * 2 + 1]);
            }
            mx = fmaxf(mx, __shfl_xor_sync(0xffffffffu, mx, 1));
            mx = fmaxf(mx, __shfl_xor_sync(0xffffffffu, mx, 2));
            float mnew = fmaxf(m[i], mx);
            float corr = __expf(m[i] - mnew);
            float rs = 0.f;
#pragma unroll
            for (int j = 0; j < 8; j++) {
                float e0 = __expf(s[j][i * 2] - mnew);
                float e1 = __expf(s[j][i * 2 + 1] - mnew);
                s[j][i * 2] = e0;
                s[j][i * 2 + 1] = e1;
                rs += e0 + e1;
            }
            rs += __shfl_xor_sync(0xffffffffu, rs, 1);
            rs += __shfl_xor_sync(0xffffffffu, rs, 2);
            l[i] = l[i] * corr + rs;
            m[i] = mnew;
#pragma unroll
            for (int j = 0; j < 8; j++) {
                o[j][i * 2] *= corr;
                o[j][i * 2 + 1] *= corr;
            }
        }

        // ---- O += P Vt ----
#pragma unroll
        for (int kk = 0; kk < 4; kk++) {
            uint32_t ph[4], pl[4];
#pragma unroll
            for (int half = 0; half < 2; half++) {
                const float* sv = s[2 * kk + half];
                split_pack(sv[0], sv[1], ph[half * 2], pl[half * 2]);
                split_pack(sv[2], sv[3], ph[half * 2 + 1], pl[half * 2 + 1]);
            }
#pragma unroll
            for (int jp = 0; jp < 4; jp++) {
                uint32_t vh4[4], vl4[4];
                uint32_t offv = fl_off(jp * 16 + b_row4, kk * 2 + b_chunk4);
                ldsm_x4(vh4, aVh + offv);
                ldsm_x4(vl4, aVl + offv);
                mma16816(o[2 * jp], ph, vh4);
                mma16816(o[2 * jp], ph, vl4);
                mma16816(o[2 * jp], pl, vh4);
                mma16816(o[2 * jp + 1], ph, vh4 + 2);
                mma16816(o[2 * jp + 1], ph, vl4 + 2);
                mma16816(o[2 * jp + 1], pl, vh4 + 2);
            }
        }
    }
#undef F_ISSUE

    // ---- Epilogue: normalize, write fp16 split O [token][dmodel] ----
    const int bb = bh >> 4;
    const int h = bh & 15;
    float inv0 = 1.f / l[0];
    float inv1 = 1.f / l[1];
#pragma unroll
    for (int j = 0; j < 8; j++) {
        int col = h * 64 + j * 8 + tig * 2;
        int r0 = q0 + wq * 16 + gid;
        size_t off0 = (size_t)(bb * SEQ + r0) * DMODEL + col;
        size_t off1 = (size_t)(bb * SEQ + r0 + 8) * DMODEL + col;
        uint32_t hh, ll;
        split_pack_f16(o[j][0] * inv0, o[j][1] * inv0, hh, ll);
        *(uint32_t*)(g_Oh + off0) = hh;
        *(uint32_t*)(g_Ol + off0) = ll;
        split_pack_f16(o[j][2] * inv1, o[j][3] * inv1, hh, ll);
        *(uint32_t*)(g_Oh + off1) = hh;
        *(uint32_t*)(g_Ol + off1) = ll;
    }
}

// ---------------------------------------------------------------------------

extern "C" void kernel_launch(void* const* d_in, const int* in_sizes, int n_in,
                              void* d_out, int out_size)
{
    (void)in_sizes; (void)n_in; (void)out_size;
    const float* x  = (const float*)d_in[0];
    const float* Wq = (const float*)d_in[1];
    const float* Wk = (const float*)d_in[2];
    const float* Wv = (const float*)d_in[3];
    const float* Wo = (const float*)d_in[4];
    float* out = (float*)d_out;

    cudaFuncSetAttribute(gemm_f16, cudaFuncAttributeMaxDynamicSharedMemorySize,
                         GEMM_SMEM_BYTES);
    cudaFuncSetAttribute(flash_mma, cudaFuncAttributeMaxDynamicSharedMemorySize,
                         F_SMEM_BYTES);

    convert_split<<<dim3(4096, 5), 256>>>(x, Wq, Wk, Wv, Wo);

    dim3 gqkv(DMODEL / 256, TOKENS / 128, 3);   // (4, 32, 3)
    gemm_f16<<<gqkv, 256, GEMM_SMEM_BYTES>>>(nullptr, 1);

    dim3 gatt(SEQ / 128, 2 * NHEADS);           // (16, 32)
    flash_mma<<<gatt, 256, F_SMEM_BYTES>>>();

    dim3 gout(DMODEL / 256, TOKENS / 128, 1);   // (4, 32)
    gemm_f16<<<gout, 256, GEMM_SMEM_BYTES>>>(out, 0);
}

// round 14
// speedup vs baseline: 1.5206x; 1.1789x over previous
#include <cuda_runtime.h>
#include <cuda_fp16.h>
#include <cstdint>

#define TOKENS 4096
#define DMODEL 1024
#define NHEADS 16
#define SEQ 2048

// X, Q, O: fp16 split (hi/lo). Weights, K, V: plain fp16.
__device__ __align__(16) __half g_Xh[TOKENS * DMODEL];
__device__ __align__(16) __half g_Xl[TOKENS * DMODEL];
__device__ __align__(16) __half g_Wq[DMODEL * DMODEL];
__device__ __align__(16) __half g_Wk[DMODEL * DMODEL];
__device__ __align__(16) __half g_Wv[DMODEL * DMODEL];
__device__ __align__(16) __half g_Wo[DMODEL * DMODEL];
// Q (pre-scaled, split) and K (plain): [B*H][S][64]. Vt (plain): [B*H][64][S].
__device__ __align__(16) __half g_Qh[TOKENS * DMODEL];
__device__ __align__(16) __half g_Ql[TOKENS * DMODEL];
__device__ __align__(16) __half g_K[TOKENS * DMODEL];
__device__ __align__(16) __half g_Vt[TOKENS * DMODEL];
// O: fp16 split [token][dmodel].
__device__ __align__(16) __half g_Oh[TOKENS * DMODEL];
__device__ __align__(16) __half g_Ol[TOKENS * DMODEL];

__device__ __forceinline__ float neg_inf() { return __int_as_float(0xff800000u); }

__device__ __forceinline__ uint32_t smem_u32(const void* p) {
    uint32_t a;
    asm("{ .reg .u64 t; cvta.to.shared.u64 t, %1; cvt.u32.u64 %0, t; }"
        : "=r"(a) : "l"(p));
    return a;
}

__device__ __forceinline__ uint32_t pack_h2(__half a, __half b) {
    return (uint32_t)__half_as_ushort(a) | ((uint32_t)__half_as_ushort(b) << 16);
}

__device__ __forceinline__ void split_pack_f16(float a, float b,
                                               uint32_t& h, uint32_t& l) {
    __half ha = __float2half_rn(a);
    __half hb = __float2half_rn(b);
    __half la = __float2half_rn(a - __half2float(ha));
    __half lb = __float2half_rn(b - __half2float(hb));
    h = pack_h2(ha, hb);
    l = pack_h2(la, lb);
}

__device__ __forceinline__ void ldsm_x4(uint32_t* r, uint32_t addr) {
    asm volatile("ldmatrix.sync.aligned.m8n8.x4.shared.b16 {%0,%1,%2,%3}, [%4];"
                 : "=r"(r[0]), "=r"(r[1]), "=r"(r[2]), "=r"(r[3]) : "r"(addr));
}

__device__ __forceinline__ void mma16816h(float* d, const uint32_t* a,
                                          const uint32_t* b) {
    asm volatile("mma.sync.aligned.m16n8k16.row.col.f32.f16.f16.f32 "
                 "{%0,%1,%2,%3}, {%4,%5,%6,%7}, {%8,%9}, {%0,%1,%2,%3};"
                 : "+f"(d[0]), "+f"(d[1]), "+f"(d[2]), "+f"(d[3])
                 : "r"(a[0]), "r"(a[1]), "r"(a[2]), "r"(a[3]),
                   "r"(b[0]), "r"(b[1]));
}

__device__ __forceinline__ void cp16(uint32_t saddr, const void* gaddr) {
    asm volatile("cp.async.cg.shared.global [%0], [%1], 16;"
                 :: "r"(saddr), "l"(gaddr));
}

__device__ __forceinline__ void cp_commit() {
    asm volatile("cp.async.commit_group;" ::: "memory");
}
__device__ __forceinline__ void cp_wait1() {
    asm volatile("cp.async.wait_group 1;" ::: "memory");
}
__device__ __forceinline__ void cp_wait0() {
    asm volatile("cp.async.wait_group 0;" ::: "memory");
}

// Full-row swizzle for 128B rows (validated in flash since r8).
__device__ __forceinline__ uint32_t fl_off(int r, int c) {
    return (uint32_t)(r * 128 + ((c ^ (r & 7)) << 4));
}

// ---------------------------------------------------------------------------
// Pre-pass: X -> fp16 hi/lo; weights -> plain fp16.
// ---------------------------------------------------------------------------

__global__ void convert_split(const float* __restrict__ x,
                              const float* __restrict__ Wq,
                              const float* __restrict__ Wk,
                              const float* __restrict__ Wv,
                              const float* __restrict__ Wo)
{
    int i = (blockIdx.x * blockDim.x + threadIdx.x) * 4;
    if (blockIdx.y == 0) {
        if (i >= TOKENS * DMODEL) return;
        float4 v = *(const float4*)(x + i);
        uint32_t h0, h1, l0, l1;
        split_pack_f16(v.x, v.y, h0, l0);
        split_pack_f16(v.z, v.w, h1, l1);
        *(uint2*)(g_Xh + i) = make_uint2(h0, h1);
        *(uint2*)(g_Xl + i) = make_uint2(l0, l1);
    } else {
        if (i >= DMODEL * DMODEL) return;
        const float* src = (blockIdx.y == 1) ? Wq :
                           (blockIdx.y == 2) ? Wk :
                           (blockIdx.y == 3) ? Wv : Wo;
        __half* dst = (blockIdx.y == 1) ? g_Wq :
                      (blockIdx.y == 2) ? g_Wk :
                      (blockIdx.y == 3) ? g_Wv : g_Wo;
        float4 v = *(const float4*)(src + i);
        uint32_t h0 = pack_h2(__float2half_rn(v.x), __float2half_rn(v.y));
        uint32_t h1 = pack_h2(__float2half_rn(v.z), __float2half_rn(v.w));
        *(uint2*)(dst + i) = make_uint2(h0, h1);
    }
}

// ---------------------------------------------------------------------------
// fp16 2-MMA HMMA GEMM: A split (h,l), B plain. CTA 128x256, BK=64, 3-stage.
// Stage: Ah 16KB | Al 16KB | B 32KB = 64KB. Rows = 64 fp16 = 128B (fl_off).
// ---------------------------------------------------------------------------

#define G_STAGE 65536
#define GEMM_SMEM_BYTES (3 * G_STAGE)

__global__ __launch_bounds__(256, 1) void gemm_f16(float* __restrict__ Cout,
                                                   int qkv_mode)
{
    extern __shared__ char sm[];
    const uint32_t sb = smem_u32(sm);
    const int tid = threadIdx.x;
    const int lane = tid & 31;
    const int wid = tid >> 5;
    const int warp_m = wid >> 2;
    const int warp_n = wid & 3;
    const int z = blockIdx.z;

    const __half *Ah, *Al, *Bp;
    if (qkv_mode) {
        Ah = g_Xh; Al = g_Xl;
        Bp = (z == 0) ? g_Wq : (z == 1 ? g_Wk : g_Wv);
    } else {
        Ah = g_Oh; Al = g_Ol; Bp = g_Wo;
    }
    const int m0 = blockIdx.y * 128;
    const int n0 = blockIdx.x * 256;
    const __half* Agh = Ah + (size_t)m0 * DMODEL;
    const __half* Agl = Al + (size_t)m0 * DMODEL;
    const __half* Bg  = Bp + (size_t)n0 * DMODEL;

    // cp.async: A 1024 chunks/array (4/thread each), B 2048 chunks (8/thread).
    int rA[4]; uint32_t oA[4];
#pragma unroll
    for (int u = 0; u < 4; u++) {
        int lin = u * 256 + tid;
        rA[u] = lin >> 3;
        oA[u] = fl_off(rA[u], lin & 7);
    }
    int rB[8]; uint32_t oB[8];
#pragma unroll
    for (int u = 0; u < 8; u++) {
        int lin = u * 256 + tid;
        rB[u] = lin >> 3;
        oB[u] = fl_off(rB[u], lin & 7);
    }
    const int cThis = (tid & 7) * 8;

    float acc[4][8][4];
#pragma unroll
    for (int i = 0; i < 4; i++)
#pragma unroll
        for (int j = 0; j < 8; j++)
#pragma unroll
            for (int u = 0; u < 4; u++) acc[i][j][u] = 0.f;

    const int a_mat = lane >> 3;
    const int a_khalf = a_mat >> 1;
    int rowA[4];
#pragma unroll
    for (int im = 0; im < 4; im++)
        rowA[im] = warp_m * 64 + im * 16 + (a_mat & 1) * 8 + (lane & 7);
    const int b_row4 = ((lane >> 4) << 3) + (lane & 7);
    const int b_chunk4 = (lane >> 3) & 1;

#define ISSUE(chv)                                                                 \
    do {                                                                           \
        const int _k0 = (chv) * 64;                                                \
        const uint32_t _bs = sb + (uint32_t)(((chv) % 3) * G_STAGE);               \
        cp16(_bs + oA[0],          Agh + (size_t)rA[0] * DMODEL + _k0 + cThis);    \
        cp16(_bs + oA[1],          Agh + (size_t)rA[1] * DMODEL + _k0 + cThis);    \
        cp16(_bs + oA[2],          Agh + (size_t)rA[2] * DMODEL + _k0 + cThis);    \
        cp16(_bs + oA[3],          Agh + (size_t)rA[3] * DMODEL + _k0 + cThis);    \
        cp16(_bs + 16384 + oA[0],  Agl + (size_t)rA[0] * DMODEL + _k0 + cThis);    \
        cp16(_bs + 16384 + oA[1],  Agl + (size_t)rA[1] * DMODEL + _k0 + cThis);    \
        cp16(_bs + 16384 + oA[2],  Agl + (size_t)rA[2] * DMODEL + _k0 + cThis);    \
        cp16(_bs + 16384 + oA[3],  Agl + (size_t)rA[3] * DMODEL + _k0 + cThis);    \
        cp16(_bs + 32768 + oB[0],  Bg + (size_t)rB[0] * DMODEL + _k0 + cThis);     \
        cp16(_bs + 32768 + oB[1],  Bg + (size_t)rB[1] * DMODEL + _k0 + cThis);     \
        cp16(_bs + 32768 + oB[2],  Bg + (size_t)rB[2] * DMODEL + _k0 + cThis);     \
        cp16(_bs + 32768 + oB[3],  Bg + (size_t)rB[3] * DMODEL + _k0 + cThis);     \
        cp16(_bs + 32768 + oB[4],  Bg + (size_t)rB[4] * DMODEL + _k0 + cThis);     \
        cp16(_bs + 32768 + oB[5],  Bg + (size_t)rB[5] * DMODEL + _k0 + cThis);     \
        cp16(_bs + 32768 + oB[6],  Bg + (size_t)rB[6] * DMODEL + _k0 + cThis);     \
        cp16(_bs + 32768 + oB[7],  Bg + (size_t)rB[7] * DMODEL + _k0 + cThis);     \
        cp_commit();                                                               \
    } while (0)

    ISSUE(0);
    ISSUE(1);

    for (int ch = 0; ch < 16; ch++) {
        if (ch + 1 < 16) cp_wait1(); else cp_wait0();
        __syncthreads();
        if (ch + 2 < 16) ISSUE(ch + 2);

        const uint32_t bs = sb + (uint32_t)((ch % 3) * G_STAGE);
        const uint32_t sAh = bs, sAl = bs + 16384;
        const uint32_t sB = bs + 32768;
#pragma unroll
        for (int kk = 0; kk < 4; kk++) {
            uint32_t ah[4][4], al[4][4];
#pragma unroll
            for (int im = 0; im < 4; im++) {
                uint32_t off = fl_off(rowA[im], kk * 2 + a_khalf);
                ldsm_x4(ah[im], sAh + off);
                ldsm_x4(al[im], sAl + off);
            }
#pragma unroll
            for (int inp = 0; inp < 4; inp++) {
                uint32_t b4[4];
                uint32_t off = fl_off(warp_n * 64 + inp * 16 + b_row4,
                                      kk * 2 + b_chunk4);
                ldsm_x4(b4, sB + off);
#pragma unroll
                for (int im = 0; im < 4; im++) {
                    mma16816h(acc[im][2 * inp], ah[im], b4);
                    mma16816h(acc[im][2 * inp], al[im], b4);
                    mma16816h(acc[im][2 * inp + 1], ah[im], b4 + 2);
                    mma16816h(acc[im][2 * inp + 1], al[im], b4 + 2);
                }
            }
        }
        __syncthreads();
    }
#undef ISSUE

    const int gid = lane >> 2;
    const int tig = lane & 3;
    if (qkv_mode) {
        if (z == 0) {
            // Q: split fp16, pre-scaled.
#pragma unroll
            for (int im = 0; im < 4; im++) {
#pragma unroll
                for (int in = 0; in < 8; in++) {
                    int row = m0 + warp_m * 64 + im * 16 + gid;
                    int col = n0 + warp_n * 64 + in * 8 + tig * 2;
                    int h = col >> 6, hd = col & 63;
#pragma unroll
                    for (int half = 0; half < 2; half++) {
                        int rr = row + half * 8;
                        int bb = rr >> 11, s = rr & 2047;
                        size_t off = (((size_t)(bb * NHEADS + h) * SEQ + s) << 6) + hd;
                        uint32_t hh, ll;
                        split_pack_f16(acc[im][in][half * 2] * 0.125f,
                                       acc[im][in][half * 2 + 1] * 0.125f, hh, ll);
                        *(uint32_t*)(g_Qh + off) = hh;
                        *(uint32_t*)(g_Ql + off) = ll;
                    }
                }
            }
        } else if (z == 1) {
            // K: plain fp16.
#pragma unroll
            for (int im = 0; im < 4; im++) {
#pragma unroll
                for (int in = 0; in < 8; in++) {
                    int row = m0 + warp_m * 64 + im * 16 + gid;
                    int col = n0 + warp_n * 64 + in * 8 + tig * 2;
                    int h = col >> 6, hd = col & 63;
#pragma unroll
                    for (int half = 0; half < 2; half++) {
                        int rr = row + half * 8;
                        int bb = rr >> 11, s = rr & 2047;
                        size_t off = (((size_t)(bb * NHEADS + h) * SEQ + s) << 6) + hd;
                        *(uint32_t*)(g_K + off) =
                            pack_h2(__float2half_rn(acc[im][in][half * 2]),
                                    __float2half_rn(acc[im][in][half * 2 + 1]));
                    }
                }
            }
        } else {
            // V: plain fp16, TRANSPOSED [bh][d][s].
#pragma unroll
            for (int im = 0; im < 4; im++) {
#pragma unroll
                for (int in = 0; in < 8; in++) {
                    int row = m0 + warp_m * 64 + im * 16 + gid;
                    int col = n0 + warp_n * 64 + in * 8 + tig * 2;
                    int h = col >> 6, hd = col & 63;
#pragma unroll
                    for (int half = 0; half < 2; half++) {
                        int rr = row + half * 8;
                        int bb = rr >> 11, s = rr & 2047;
                        size_t base = ((size_t)(bb * NHEADS + h) * 64 + hd) * SEQ + s;
                        g_Vt[base]       = __float2half_rn(acc[im][in][half * 2]);
                        g_Vt[base + SEQ] = __float2half_rn(acc[im][in][half * 2 + 1]);
                    }
                }
            }
        }
    } else {
#pragma unroll
        for (int im = 0; im < 4; im++) {
#pragma unroll
            for (int in = 0; in < 8; in++) {
                int row = m0 + warp_m * 64 + im * 16 + gid;
                int col = n0 + warp_n * 64 + in * 8 + tig * 2;
#pragma unroll
                for (int half = 0; half < 2; half++) {
                    int rr = row + half * 8;
                    float* dst = Cout + (size_t)rr * DMODEL + col;
                    dst[0] = acc[im][in][half * 2 + 0];
                    dst[1] = acc[im][in][half * 2 + 1];
                }
            }
        }
    }
}

// ---------------------------------------------------------------------------
// Flash attention (causal), fp16 2-MMA. Br=128, Bc=64, 8 warps.
// Q split fp16 (hoisted frags); K, Vt plain fp16; P split fp16.
// Smem: Q 32KB | 3 stages x (K 8KB + Vt 8KB) = 80KB dynamic.
// ---------------------------------------------------------------------------

#define F_SMEM_BYTES (32768 + 3 * 16384)

__global__ __launch_bounds__(256, 1) void flash_mma()
{
    extern __shared__ char sm[];
    const uint32_t sb = smem_u32(sm);
    const int tid = threadIdx.x;
    const int lane = tid & 31;
    const int wq = tid >> 5;
    const int qt = gridDim.x - 1 - blockIdx.x;   // longest first
    const int bh = blockIdx.y;
    const int q0 = qt * 128;
    const int T = 2 * qt + 2;

    const __half* qbh = g_Qh + (size_t)(bh * SEQ + q0) * 64;
    const __half* qbl = g_Ql + (size_t)(bh * SEQ + q0) * 64;
    const __half* kbp = g_K + (size_t)bh * SEQ * 64;
    const __half* vtp = g_Vt + (size_t)bh * 64 * SEQ;

    const uint32_t aQh = sb, aQl = sb + 16384;

#pragma unroll
    for (int u = 0; u < 4; u++) {
        int lin = u * 256 + tid;
        int r = lin >> 3, c = lin & 7;
        uint32_t off = fl_off(r, c);
        *(uint4*)(sm + off)         = *(const uint4*)(qbh + r * 64 + c * 8);
        *(uint4*)(sm + 16384 + off) = *(const uint4*)(qbl + r * 64 + c * 8);
    }

    int rF[2]; uint32_t oF[2];
#pragma unroll
    for (int u = 0; u < 2; u++) {
        int lin = u * 256 + tid;
        rF[u] = lin >> 3;
        oF[u] = fl_off(rF[u], lin & 7);
    }
    const int cF0 = (tid & 7) * 8, cF1 = ((256 + tid) & 7) * 8;

#define F_ISSUE(tt)                                                                \
    do {                                                                           \
        const uint32_t _bs = sb + 32768u + (uint32_t)(((tt) % 3) * 16384);         \
        cp16(_bs + oF[0],        kbp + (size_t)((tt) * 64 + rF[0]) * 64 + cF0);    \
        cp16(_bs + oF[1],        kbp + (size_t)((tt) * 64 + rF[1]) * 64 + cF1);    \
        cp16(_bs + 8192 + oF[0], vtp + (size_t)rF[0] * SEQ + (tt) * 64 + cF0);     \
        cp16(_bs + 8192 + oF[1], vtp + (size_t)rF[1] * SEQ + (tt) * 64 + cF1);     \
        cp_commit();                                                               \
    } while (0)

    F_ISSUE(0);
    F_ISSUE(1);   // T >= 2 always

    const int a_mat = lane >> 3;
    const int a_khalf = a_mat >> 1;
    const int rowA = wq * 16 + (a_mat & 1) * 8 + (lane & 7);
    const int b_row4 = ((lane >> 4) << 3) + (lane & 7);
    const int b_chunk4 = (lane >> 3) & 1;
    const int gid = lane >> 2;
    const int tig = lane & 3;

    // ---- Hoist Q fragments (loop-invariant) ----
    __syncthreads();
    uint32_t qh[4][4], ql[4][4];
#pragma unroll
    for (int kk = 0; kk < 4; kk++) {
        uint32_t offa = fl_off(rowA, kk * 2 + a_khalf);
        ldsm_x4(qh[kk], aQh + offa);
        ldsm_x4(ql[kk], aQl + offa);
    }

    float m[2], l[2], o[8][4], s[8][4];
#pragma unroll
    for (int i = 0; i < 2; i++) { m[i] = neg_inf(); l[i] = 0.f; }
#pragma unroll
    for (int j = 0; j < 8; j++)
#pragma unroll
        for (int u = 0; u < 4; u++) o[j][u] = 0.f;

    for (int t = 0; t < T; t++) {
        if (t + 1 < T) cp_wait1(); else cp_wait0();
        __syncthreads();
        if (t + 2 < T) F_ISSUE(t + 2);

        const uint32_t bs = sb + 32768u + (uint32_t)((t % 3) * 16384);
        const uint32_t aK = bs, aV = bs + 8192;

        // ---- S = Q K^T ----
#pragma unroll
        for (int j = 0; j < 8; j++)
#pragma unroll
            for (int u = 0; u < 4; u++) s[j][u] = 0.f;

#pragma unroll
        for (int kk = 0; kk < 4; kk++) {
#pragma unroll
            for (int jp = 0; jp < 4; jp++) {
                uint32_t b4[4];
                uint32_t offb = fl_off(jp * 16 + b_row4, kk * 2 + b_chunk4);
                ldsm_x4(b4, aK + offb);
                mma16816h(s[2 * jp], qh[kk], b4);
                mma16816h(s[2 * jp], ql[kk], b4);
                mma16816h(s[2 * jp + 1], qh[kk], b4 + 2);
                mma16816h(s[2 * jp + 1], ql[kk], b4 + 2);
            }
        }

        if (t >= 2 * qt) {
#pragma unroll
            for (int j = 0; j < 8; j++) {
#pragma unroll
                for (int u = 0; u < 4; u++) {
                    int row = q0 + wq * 16 + (u >> 1) * 8 + gid;
                    int col = t * 64 + j * 8 + tig * 2 + (u & 1);
                    if (col > row) s[j][u] = neg_inf();
                }
            }
        }

        // ---- Online softmax ----
#pragma unroll
        for (int i = 0; i < 2; i++) {
            float mx = neg_inf();
#pragma unroll
            for (int j = 0; j < 8; j++) {
                mx = fmaxf(mx, s[j][i * 2]);
                mx = fmaxf(mx, s[j][i * 2 + 1]);
            }
            mx = fmaxf(mx, __shfl_xor_sync(0xffffffffu, mx, 1));
            mx = fmaxf(mx, __shfl_xor_sync(0xffffffffu, mx, 2));
            float mnew = fmaxf(m[i], mx);
            float corr = __expf(m[i] - mnew);
            float rs = 0.f;
#pragma unroll
            for (int j = 0; j < 8; j++) {
                float e0 = __expf(s[j][i * 2] - mnew);
                float e1 = __expf(s[j][i * 2 + 1] - mnew);
                s[j][i * 2] = e0;
                s[j][i * 2 + 1] = e1;
                rs += e0 + e1;
            }
            rs += __shfl_xor_sync(0xffffffffu, rs, 1);
            rs += __shfl_xor_sync(0xffffffffu, rs, 2);
            l[i] = l[i] * corr + rs;
            m[i] = mnew;
#pragma unroll
            for (int j = 0; j < 8; j++) {
                o[j][i * 2] *= corr;
                o[j][i * 2 + 1] *= corr;
            }
        }

        // ---- O += P Vt (P split fp16) ----
#pragma unroll
        for (int kk = 0; kk < 4; kk++) {
            uint32_t ph[4], pl[4];
#pragma unroll
            for (int half = 0; half < 2; half++) {
                const float* sv = s[2 * kk + half];
                split_pack_f16(sv[0], sv[1], ph[half * 2], pl[half * 2]);
                split_pack_f16(sv[2], sv[3], ph[half * 2 + 1], pl[half * 2 + 1]);
            }
#pragma unroll
            for (int jp = 0; jp < 4; jp++) {
                uint32_t v4[4];
                uint32_t offv = fl_off(jp * 16 + b_row4, kk * 2 + b_chunk4);
                ldsm_x4(v4, aV + offv);
                mma16816h(o[2 * jp], ph, v4);
                mma16816h(o[2 * jp], pl, v4);
                mma16816h(o[2 * jp + 1], ph, v4 + 2);
                mma16816h(o[2 * jp + 1], pl, v4 + 2);
            }
        }
    }
#undef F_ISSUE

    // ---- Epilogue: normalize, write fp16 split O [token][dmodel] ----
    const int bb = bh >> 4;
    const int h = bh & 15;
    float inv0 = 1.f / l[0];
    float inv1 = 1.f / l[1];
#pragma unroll
    for (int j = 0; j < 8; j++) {
        int col = h * 64 + j * 8 + tig * 2;
        int r0 = q0 + wq * 16 + gid;
        size_t off0 = (size_t)(bb * SEQ + r0) * DMODEL + col;
        size_t off1 = (size_t)(bb * SEQ + r0 + 8) * DMODEL + col;
        uint32_t hh, ll;
        split_pack_f16(o[j][0] * inv0, o[j][1] * inv0, hh, ll);
        *(uint32_t*)(g_Oh + off0) = hh;
        *(uint32_t*)(g_Ol + off0) = ll;
        split_pack_f16(o[j][2] * inv1, o[j][3] * inv1, hh, ll);
        *(uint32_t*)(g_Oh + off1) = hh;
        *(uint32_t*)(g_Ol + off1) = ll;
    }
}

// ---------------------------------------------------------------------------

extern "C" void kernel_launch(void* const* d_in, const int* in_sizes, int n_in,
                              void* d_out, int out_size)
{
    (void)in_sizes; (void)n_in; (void)out_size;
    const float* x  = (const float*)d_in[0];
    const float* Wq = (const float*)d_in[1];
    const float* Wk = (const float*)d_in[2];
    const float* Wv = (const float*)d_in[3];
    const float* Wo = (const float*)d_in[4];
    float* out = (float*)d_out;

    cudaFuncSetAttribute(gemm_f16, cudaFuncAttributeMaxDynamicSharedMemorySize,
                         GEMM_SMEM_BYTES);
    cudaFuncSetAttribute(flash_mma, cudaFuncAttributeMaxDynamicSharedMemorySize,
                         F_SMEM_BYTES);

    convert_split<<<dim3(4096, 5), 256>>>(x, Wq, Wk, Wv, Wo);

    dim3 gqkv(DMODEL / 256, TOKENS / 128, 3);   // (4, 32, 3)
    gemm_f16<<<gqkv, 256, GEMM_SMEM_BYTES>>>(nullptr, 1);

    dim3 gatt(SEQ / 128, 2 * NHEADS);           // (16, 32)
    flash_mma<<<gatt, 256, F_SMEM_BYTES>>>();

    dim3 gout(DMODEL / 256, TOKENS / 128, 1);   // (4, 32)
    gemm_f16<<<gout, 256, GEMM_SMEM_BYTES>>>(out, 0);
}

// round 15
// speedup vs baseline: 1.5423x; 1.0142x over previous
#include <cuda_runtime.h>
#include <cuda_fp16.h>
#include <cstdint>

#define TOKENS 4096
#define DMODEL 1024
#define NHEADS 16
#define SEQ 2048

// X, Q, O: fp16 split (hi/lo). Weights, K, V: plain fp16.
__device__ __align__(16) __half g_Xh[TOKENS * DMODEL];
__device__ __align__(16) __half g_Xl[TOKENS * DMODEL];
__device__ __align__(16) __half g_Wq[DMODEL * DMODEL];
__device__ __align__(16) __half g_Wk[DMODEL * DMODEL];
__device__ __align__(16) __half g_Wv[DMODEL * DMODEL];
__device__ __align__(16) __half g_Wo[DMODEL * DMODEL];
// Q (pre-scaled, split) and K (plain): [B*H][S][64]. Vt (plain): [B*H][64][S].
__device__ __align__(16) __half g_Qh[TOKENS * DMODEL];
__device__ __align__(16) __half g_Ql[TOKENS * DMODEL];
__device__ __align__(16) __half g_K[TOKENS * DMODEL];
__device__ __align__(16) __half g_Vt[TOKENS * DMODEL];
// O: fp16 split [token][dmodel].
__device__ __align__(16) __half g_Oh[TOKENS * DMODEL];
__device__ __align__(16) __half g_Ol[TOKENS * DMODEL];

__device__ __forceinline__ float neg_inf() { return __int_as_float(0xff800000u); }

__device__ __forceinline__ uint32_t smem_u32(const void* p) {
    uint32_t a;
    asm("{ .reg .u64 t; cvta.to.shared.u64 t, %1; cvt.u32.u64 %0, t; }"
        : "=r"(a) : "l"(p));
    return a;
}

__device__ __forceinline__ uint32_t pack_h2(__half a, __half b) {
    return (uint32_t)__half_as_ushort(a) | ((uint32_t)__half_as_ushort(b) << 16);
}

__device__ __forceinline__ void split_pack_f16(float a, float b,
                                               uint32_t& h, uint32_t& l) {
    __half ha = __float2half_rn(a);
    __half hb = __float2half_rn(b);
    __half la = __float2half_rn(a - __half2float(ha));
    __half lb = __float2half_rn(b - __half2float(hb));
    h = pack_h2(ha, hb);
    l = pack_h2(la, lb);
}

__device__ __forceinline__ void ldsm_x4(uint32_t* r, uint32_t addr) {
    asm volatile("ldmatrix.sync.aligned.m8n8.x4.shared.b16 {%0,%1,%2,%3}, [%4];"
                 : "=r"(r[0]), "=r"(r[1]), "=r"(r[2]), "=r"(r[3]) : "r"(addr));
}

__device__ __forceinline__ void mma16816h(float* d, const uint32_t* a,
                                          const uint32_t* b) {
    asm volatile("mma.sync.aligned.m16n8k16.row.col.f32.f16.f16.f32 "
                 "{%0,%1,%2,%3}, {%4,%5,%6,%7}, {%8,%9}, {%0,%1,%2,%3};"
                 : "+f"(d[0]), "+f"(d[1]), "+f"(d[2]), "+f"(d[3])
                 : "r"(a[0]), "r"(a[1]), "r"(a[2]), "r"(a[3]),
                   "r"(b[0]), "r"(b[1]));
}

__device__ __forceinline__ void cp16(uint32_t saddr, const void* gaddr) {
    asm volatile("cp.async.cg.shared.global [%0], [%1], 16;"
                 :: "r"(saddr), "l"(gaddr));
}

__device__ __forceinline__ void cp_commit() {
    asm volatile("cp.async.commit_group;" ::: "memory");
}
__device__ __forceinline__ void cp_wait1() {
    asm volatile("cp.async.wait_group 1;" ::: "memory");
}
__device__ __forceinline__ void cp_wait0() {
    asm volatile("cp.async.wait_group 0;" ::: "memory");
}

// Full-row swizzle for 128B rows.
__device__ __forceinline__ uint32_t fl_off(int r, int c) {
    return (uint32_t)(r * 128 + ((c ^ (r & 7)) << 4));
}

// ---------------------------------------------------------------------------
// Pre-pass: X -> fp16 hi/lo; weights -> plain fp16.
// ---------------------------------------------------------------------------

__global__ void convert_split(const float* __restrict__ x,
                              const float* __restrict__ Wq,
                              const float* __restrict__ Wk,
                              const float* __restrict__ Wv,
                              const float* __restrict__ Wo)
{
    int i = (blockIdx.x * blockDim.x + threadIdx.x) * 4;
    if (blockIdx.y == 0) {
        if (i >= TOKENS * DMODEL) return;
        float4 v = *(const float4*)(x + i);
        uint32_t h0, h1, l0, l1;
        split_pack_f16(v.x, v.y, h0, l0);
        split_pack_f16(v.z, v.w, h1, l1);
        *(uint2*)(g_Xh + i) = make_uint2(h0, h1);
        *(uint2*)(g_Xl + i) = make_uint2(l0, l1);
    } else {
        if (i >= DMODEL * DMODEL) return;
        const float* src = (blockIdx.y == 1) ? Wq :
                           (blockIdx.y == 2) ? Wk :
                           (blockIdx.y == 3) ? Wv : Wo;
        __half* dst = (blockIdx.y == 1) ? g_Wq :
                      (blockIdx.y == 2) ? g_Wk :
                      (blockIdx.y == 3) ? g_Wv : g_Wo;
        float4 v = *(const float4*)(src + i);
        uint32_t h0 = pack_h2(__float2half_rn(v.x), __float2half_rn(v.y));
        uint32_t h1 = pack_h2(__float2half_rn(v.z), __float2half_rn(v.w));
        *(uint2*)(dst + i) = make_uint2(h0, h1);
    }
}

// ---------------------------------------------------------------------------
// fp16 2-MMA HMMA GEMM: A split (h,l), B plain. CTA 128x128, BK=64, 2-stage,
// 2 CTAs/SM (4 warps/SMSP for latency hiding). Warp tile 64x32.
// Stage: Ah 16KB | Al 16KB | B 16KB = 48KB.
// ---------------------------------------------------------------------------

#define G_STAGE 49152
#define GEMM_SMEM_BYTES (2 * G_STAGE)

__global__ __launch_bounds__(256, 2) void gemm_f16(float* __restrict__ Cout,
                                                   int qkv_mode)
{
    extern __shared__ char sm[];
    const uint32_t sb = smem_u32(sm);
    const int tid = threadIdx.x;
    const int lane = tid & 31;
    const int wid = tid >> 5;
    const int warp_m = wid >> 2;   // 0..1 -> 64 rows
    const int warp_n = wid & 3;    // 0..3 -> 32 cols
    const int z = blockIdx.z;

    const __half *Ah, *Al, *Bp;
    if (qkv_mode) {
        Ah = g_Xh; Al = g_Xl;
        Bp = (z == 0) ? g_Wq : (z == 1 ? g_Wk : g_Wv);
    } else {
        Ah = g_Oh; Al = g_Ol; Bp = g_Wo;
    }
    const int m0 = blockIdx.y * 128;
    const int n0 = blockIdx.x * 128;
    const __half* Agh = Ah + (size_t)m0 * DMODEL;
    const __half* Agl = Al + (size_t)m0 * DMODEL;
    const __half* Bg  = Bp + (size_t)n0 * DMODEL;

    // cp.async: each of Ah/Al/B = 128 rows x 128B = 1024 chunks -> 4/thread.
    int rT[4]; uint32_t oT[4];
#pragma unroll
    for (int u = 0; u < 4; u++) {
        int lin = u * 256 + tid;
        rT[u] = lin >> 3;
        oT[u] = fl_off(rT[u], lin & 7);
    }
    const int cThis = (tid & 7) * 8;

    float acc[4][4][4];
#pragma unroll
    for (int i = 0; i < 4; i++)
#pragma unroll
        for (int j = 0; j < 4; j++)
#pragma unroll
            for (int u = 0; u < 4; u++) acc[i][j][u] = 0.f;

    const int a_mat = lane >> 3;
    const int a_khalf = a_mat >> 1;
    int rowA[4];
#pragma unroll
    for (int im = 0; im < 4; im++)
        rowA[im] = warp_m * 64 + im * 16 + (a_mat & 1) * 8 + (lane & 7);
    const int b_row4 = ((lane >> 4) << 3) + (lane & 7);
    const int b_chunk4 = (lane >> 3) & 1;

#define ISSUE(chv)                                                                 \
    do {                                                                           \
        const int _k0 = (chv) * 64;                                                \
        const uint32_t _bs = sb + (uint32_t)(((chv) & 1) * G_STAGE);               \
        cp16(_bs + oT[0],          Agh + (size_t)rT[0] * DMODEL + _k0 + cThis);    \
        cp16(_bs + oT[1],          Agh + (size_t)rT[1] * DMODEL + _k0 + cThis);    \
        cp16(_bs + oT[2],          Agh + (size_t)rT[2] * DMODEL + _k0 + cThis);    \
        cp16(_bs + oT[3],          Agh + (size_t)rT[3] * DMODEL + _k0 + cThis);    \
        cp16(_bs + 16384 + oT[0],  Agl + (size_t)rT[0] * DMODEL + _k0 + cThis);    \
        cp16(_bs + 16384 + oT[1],  Agl + (size_t)rT[1] * DMODEL + _k0 + cThis);    \
        cp16(_bs + 16384 + oT[2],  Agl + (size_t)rT[2] * DMODEL + _k0 + cThis);    \
        cp16(_bs + 16384 + oT[3],  Agl + (size_t)rT[3] * DMODEL + _k0 + cThis);    \
        cp16(_bs + 32768 + oT[0],  Bg + (size_t)rT[0] * DMODEL + _k0 + cThis);     \
        cp16(_bs + 32768 + oT[1],  Bg + (size_t)rT[1] * DMODEL + _k0 + cThis);     \
        cp16(_bs + 32768 + oT[2],  Bg + (size_t)rT[2] * DMODEL + _k0 + cThis);     \
        cp16(_bs + 32768 + oT[3],  Bg + (size_t)rT[3] * DMODEL + _k0 + cThis);     \
        cp_commit();                                                               \
    } while (0)

    ISSUE(0);

    for (int ch = 0; ch < 16; ch++) {
        if (ch + 1 < 16) {
            ISSUE(ch + 1);
            cp_wait1();
        } else {
            cp_wait0();
        }
        __syncthreads();

        const uint32_t bs = sb + (uint32_t)((ch & 1) * G_STAGE);
        const uint32_t sAh = bs, sAl = bs + 16384;
        const uint32_t sB = bs + 32768;
#pragma unroll
        for (int kk = 0; kk < 4; kk++) {
            uint32_t ah[4][4], al[4][4];
#pragma unroll
            for (int im = 0; im < 4; im++) {
                uint32_t off = fl_off(rowA[im], kk * 2 + a_khalf);
                ldsm_x4(ah[im], sAh + off);
                ldsm_x4(al[im], sAl + off);
            }
#pragma unroll
            for (int inp = 0; inp < 2; inp++) {
                uint32_t b4[4];
                uint32_t off = fl_off(warp_n * 32 + inp * 16 + b_row4,
                                      kk * 2 + b_chunk4);
                ldsm_x4(b4, sB + off);
#pragma unroll
                for (int im = 0; im < 4; im++) {
                    mma16816h(acc[im][2 * inp], ah[im], b4);
                    mma16816h(acc[im][2 * inp], al[im], b4);
                    mma16816h(acc[im][2 * inp + 1], ah[im], b4 + 2);
                    mma16816h(acc[im][2 * inp + 1], al[im], b4 + 2);
                }
            }
        }
        __syncthreads();
    }
#undef ISSUE

    const int gid = lane >> 2;
    const int tig = lane & 3;
    if (qkv_mode) {
        if (z == 0) {
            // Q: split fp16, pre-scaled.
#pragma unroll
            for (int im = 0; im < 4; im++) {
#pragma unroll
                for (int in = 0; in < 4; in++) {
                    int row = m0 + warp_m * 64 + im * 16 + gid;
                    int col = n0 + warp_n * 32 + in * 8 + tig * 2;
                    int h = col >> 6, hd = col & 63;
#pragma unroll
                    for (int half = 0; half < 2; half++) {
                        int rr = row + half * 8;
                        int bb = rr >> 11, s = rr & 2047;
                        size_t off = (((size_t)(bb * NHEADS + h) * SEQ + s) << 6) + hd;
                        uint32_t hh, ll;
                        split_pack_f16(acc[im][in][half * 2] * 0.125f,
                                       acc[im][in][half * 2 + 1] * 0.125f, hh, ll);
                        *(uint32_t*)(g_Qh + off) = hh;
                        *(uint32_t*)(g_Ql + off) = ll;
                    }
                }
            }
        } else if (z == 1) {
            // K: plain fp16.
#pragma unroll
            for (int im = 0; im < 4; im++) {
#pragma unroll
                for (int in = 0; in < 4; in++) {
                    int row = m0 + warp_m * 64 + im * 16 + gid;
                    int col = n0 + warp_n * 32 + in * 8 + tig * 2;
                    int h = col >> 6, hd = col & 63;
#pragma unroll
                    for (int half = 0; half < 2; half++) {
                        int rr = row + half * 8;
                        int bb = rr >> 11, s = rr & 2047;
                        size_t off = (((size_t)(bb * NHEADS + h) * SEQ + s) << 6) + hd;
                        *(uint32_t*)(g_K + off) =
                            pack_h2(__float2half_rn(acc[im][in][half * 2]),
                                    __float2half_rn(acc[im][in][half * 2 + 1]));
                    }
                }
            }
        } else {
            // V: plain fp16, TRANSPOSED [bh][d][s].
#pragma unroll
            for (int im = 0; im < 4; im++) {
#pragma unroll
                for (int in = 0; in < 4; in++) {
                    int row = m0 + warp_m * 64 + im * 16 + gid;
                    int col = n0 + warp_n * 32 + in * 8 + tig * 2;
                    int h = col >> 6, hd = col & 63;
#pragma unroll
                    for (int half = 0; half < 2; half++) {
                        int rr = row + half * 8;
                        int bb = rr >> 11, s = rr & 2047;
                        size_t base = ((size_t)(bb * NHEADS + h) * 64 + hd) * SEQ + s;
                        g_Vt[base]       = __float2half_rn(acc[im][in][half * 2]);
                        g_Vt[base + SEQ] = __float2half_rn(acc[im][in][half * 2 + 1]);
                    }
                }
            }
        }
    } else {
#pragma unroll
        for (int im = 0; im < 4; im++) {
#pragma unroll
            for (int in = 0; in < 4; in++) {
                int row = m0 + warp_m * 64 + im * 16 + gid;
                int col = n0 + warp_n * 32 + in * 8 + tig * 2;
#pragma unroll
                for (int half = 0; half < 2; half++) {
                    int rr = row + half * 8;
                    float* dst = Cout + (size_t)rr * DMODEL + col;
                    dst[0] = acc[im][in][half * 2 + 0];
                    dst[1] = acc[im][in][half * 2 + 1];
                }
            }
        }
    }
}

// ---------------------------------------------------------------------------
// Flash attention (causal), fp16 2-MMA. Br=128, Bc=64, 8 warps. (unchanged r14)
// Smem: Q 32KB | 3 stages x (K 8KB + Vt 8KB) = 80KB dynamic.
// ---------------------------------------------------------------------------

#define F_SMEM_BYTES (32768 + 3 * 16384)

__global__ __launch_bounds__(256, 1) void flash_mma()
{
    extern __shared__ char sm[];
    const uint32_t sb = smem_u32(sm);
    const int tid = threadIdx.x;
    const int lane = tid & 31;
    const int wq = tid >> 5;
    const int qt = gridDim.x - 1 - blockIdx.x;   // longest first
    const int bh = blockIdx.y;
    const int q0 = qt * 128;
    const int T = 2 * qt + 2;

    const __half* qbh = g_Qh + (size_t)(bh * SEQ + q0) * 64;
    const __half* qbl = g_Ql + (size_t)(bh * SEQ + q0) * 64;
    const __half* kbp = g_K + (size_t)bh * SEQ * 64;
    const __half* vtp = g_Vt + (size_t)bh * 64 * SEQ;

    const uint32_t aQh = sb, aQl = sb + 16384;

#pragma unroll
    for (int u = 0; u < 4; u++) {
        int lin = u * 256 + tid;
        int r = lin >> 3, c = lin & 7;
        uint32_t off = fl_off(r, c);
        *(uint4*)(sm + off)         = *(const uint4*)(qbh + r * 64 + c * 8);
        *(uint4*)(sm + 16384 + off) = *(const uint4*)(qbl + r * 64 + c * 8);
    }

    int rF[2]; uint32_t oF[2];
#pragma unroll
    for (int u = 0; u < 2; u++) {
        int lin = u * 256 + tid;
        rF[u] = lin >> 3;
        oF[u] = fl_off(rF[u], lin & 7);
    }
    const int cF0 = (tid & 7) * 8, cF1 = ((256 + tid) & 7) * 8;

#define F_ISSUE(tt)                                                                \
    do {                                                                           \
        const uint32_t _bs = sb + 32768u + (uint32_t)(((tt) % 3) * 16384);         \
        cp16(_bs + oF[0],        kbp + (size_t)((tt) * 64 + rF[0]) * 64 + cF0);    \
        cp16(_bs + oF[1],        kbp + (size_t)((tt) * 64 + rF[1]) * 64 + cF1);    \
        cp16(_bs + 8192 + oF[0], vtp + (size_t)rF[0] * SEQ + (tt) * 64 + cF0);     \
        cp16(_bs + 8192 + oF[1], vtp + (size_t)rF[1] * SEQ + (tt) * 64 + cF1);     \
        cp_commit();                                                               \
    } while (0)

    F_ISSUE(0);
    F_ISSUE(1);   // T >= 2 always

    const int a_mat = lane >> 3;
    const int a_khalf = a_mat >> 1;
    const int rowA = wq * 16 + (a_mat & 1) * 8 + (lane & 7);
    const int b_row4 = ((lane >> 4) << 3) + (lane & 7);
    const int b_chunk4 = (lane >> 3) & 1;
    const int gid = lane >> 2;
    const int tig = lane & 3;

    // ---- Hoist Q fragments (loop-invariant) ----
    __syncthreads();
    uint32_t qh[4][4], ql[4][4];
#pragma unroll
    for (int kk = 0; kk < 4; kk++) {
        uint32_t offa = fl_off(rowA, kk * 2 + a_khalf);
        ldsm_x4(qh[kk], aQh + offa);
        ldsm_x4(ql[kk], aQl + offa);
    }

    float m[2], l[2], o[8][4], s[8][4];
#pragma unroll
    for (int i = 0; i < 2; i++) { m[i] = neg_inf(); l[i] = 0.f; }
#pragma unroll
    for (int j = 0; j < 8; j++)
#pragma unroll
        for (int u = 0; u < 4; u++) o[j][u] = 0.f;

    for (int t = 0; t < T; t++) {
        if (t + 1 < T) cp_wait1(); else cp_wait0();
        __syncthreads();
        if (t + 2 < T) F_ISSUE(t + 2);

        const uint32_t bs = sb + 32768u + (uint32_t)((t % 3) * 16384);
        const uint32_t aK = bs, aV = bs + 8192;

        // ---- S = Q K^T ----
#pragma unroll
        for (int j = 0; j < 8; j++)
#pragma unroll
            for (int u = 0; u < 4; u++) s[j][u] = 0.f;

#pragma unroll
        for (int kk = 0; kk < 4; kk++) {
#pragma unroll
            for (int jp = 0; jp < 4; jp++) {
                uint32_t b4[4];
                uint32_t offb = fl_off(jp * 16 + b_row4, kk * 2 + b_chunk4);
                ldsm_x4(b4, aK + offb);
                mma16816h(s[2 * jp], qh[kk], b4);
                mma16816h(s[2 * jp], ql[kk], b4);
                mma16816h(s[2 * jp + 1], qh[kk], b4 + 2);
                mma16816h(s[2 * jp + 1], ql[kk], b4 + 2);
            }
        }

        if (t >= 2 * qt) {
#pragma unroll
            for (int j = 0; j < 8; j++) {
#pragma unroll
                for (int u = 0; u < 4; u++) {
                    int row = q0 + wq * 16 + (u >> 1) * 8 + gid;
                    int col = t * 64 + j * 8 + tig * 2 + (u & 1);
                    if (col > row) s[j][u] = neg_inf();
                }
            }
        }

        // ---- Online softmax ----
#pragma unroll
        for (int i = 0; i < 2; i++) {
            float mx = neg_inf();
#pragma unroll
            for (int j = 0; j < 8; j++) {
                mx = fmaxf(mx, s[j][i * 2]);
                mx = fmaxf(mx, s[j][i * 2 + 1]);
            }
            mx = fmaxf(mx, __shfl_xor_sync(0xffffffffu, mx, 1));
            mx = fmaxf(mx, __shfl_xor_sync(0xffffffffu, mx, 2));
            float mnew = fmaxf(m[i], mx);
            float corr = __expf(m[i] - mnew);
            float rs = 0.f;
#pragma unroll
            for (int j = 0; j < 8; j++) {
                float e0 = __expf(s[j][i * 2] - mnew);
                float e1 = __expf(s[j][i * 2 + 1] - mnew);
                s[j][i * 2] = e0;
                s[j][i * 2 + 1] = e1;
                rs += e0 + e1;
            }
            rs += __shfl_xor_sync(0xffffffffu, rs, 1);
            rs += __shfl_xor_sync(0xffffffffu, rs, 2);
            l[i] = l[i] * corr + rs;
            m[i] = mnew;
#pragma unroll
            for (int j = 0; j < 8; j++) {
                o[j][i * 2] *= corr;
                o[j][i * 2 + 1] *= corr;
            }
        }

        // ---- O += P Vt (P split fp16) ----
#pragma unroll
        for (int kk = 0; kk < 4; kk++) {
            uint32_t ph[4], pl[4];
#pragma unroll
            for (int half = 0; half < 2; half++) {
                const float* sv = s[2 * kk + half];
                split_pack_f16(sv[0], sv[1], ph[half * 2], pl[half * 2]);
                split_pack_f16(sv[2], sv[3], ph[half * 2 + 1], pl[half * 2 + 1]);
            }
#pragma unroll
            for (int jp = 0; jp < 4; jp++) {
                uint32_t v4[4];
                uint32_t offv = fl_off(jp * 16 + b_row4, kk * 2 + b_chunk4);
                ldsm_x4(v4, aV + offv);
                mma16816h(o[2 * jp], ph, v4);
                mma16816h(o[2 * jp], pl, v4);
                mma16816h(o[2 * jp + 1], ph, v4 + 2);
                mma16816h(o[2 * jp + 1], pl, v4 + 2);
            }
        }
    }
#undef F_ISSUE

    // ---- Epilogue: normalize, write fp16 split O [token][dmodel] ----
    const int bb = bh >> 4;
    const int h = bh & 15;
    float inv0 = 1.f / l[0];
    float inv1 = 1.f / l[1];
#pragma unroll
    for (int j = 0; j < 8; j++) {
        int col = h * 64 + j * 8 + tig * 2;
        int r0 = q0 + wq * 16 + gid;
        size_t off0 = (size_t)(bb * SEQ + r0) * DMODEL + col;
        size_t off1 = (size_t)(bb * SEQ + r0 + 8) * DMODEL + col;
        uint32_t hh, ll;
        split_pack_f16(o[j][0] * inv0, o[j][1] * inv0, hh, ll);
        *(uint32_t*)(g_Oh + off0) = hh;
        *(uint32_t*)(g_Ol + off0) = ll;
        split_pack_f16(o[j][2] * inv1, o[j][3] * inv1, hh, ll);
        *(uint32_t*)(g_Oh + off1) = hh;
        *(uint32_t*)(g_Ol + off1) = ll;
    }
}

// ---------------------------------------------------------------------------

extern "C" void kernel_launch(void* const* d_in, const int* in_sizes, int n_in,
                              void* d_out, int out_size)
{
    (void)in_sizes; (void)n_in; (void)out_size;
    const float* x  = (const float*)d_in[0];
    const float* Wq = (const float*)d_in[1];
    const float* Wk = (const float*)d_in[2];
    const float* Wv = (const float*)d_in[3];
    const float* Wo = (const float*)d_in[4];
    float* out = (float*)d_out;

    cudaFuncSetAttribute(gemm_f16, cudaFuncAttributeMaxDynamicSharedMemorySize,
                         GEMM_SMEM_BYTES);
    cudaFuncSetAttribute(flash_mma, cudaFuncAttributeMaxDynamicSharedMemorySize,
                         F_SMEM_BYTES);

    convert_split<<<dim3(4096, 5), 256>>>(x, Wq, Wk, Wv, Wo);

    dim3 gqkv(DMODEL / 128, TOKENS / 128, 3);   // (8, 32, 3)
    gemm_f16<<<gqkv, 256, GEMM_SMEM_BYTES>>>(nullptr, 1);

    dim3 gatt(SEQ / 128, 2 * NHEADS);           // (16, 32)
    flash_mma<<<gatt, 256, F_SMEM_BYTES>>>();

    dim3 gout(DMODEL / 128, TOKENS / 128, 1);   // (8, 32)
    gemm_f16<<<gout, 256, GEMM_SMEM_BYTES>>>(out, 0);
}

// round 17
// speedup vs baseline: 1.6690x; 1.0822x over previous
#include <cuda_runtime.h>
#include <cuda_fp16.h>
#include <cstdint>

#define TOKENS 4096
#define DMODEL 1024
#define NHEADS 16
#define SEQ 2048

// X, Q, O: fp16 split (hi/lo). Weights, K, V: plain fp16.
__device__ __align__(16) __half g_Xh[TOKENS * DMODEL];
__device__ __align__(16) __half g_Xl[TOKENS * DMODEL];
__device__ __align__(16) __half g_Wq[DMODEL * DMODEL];
__device__ __align__(16) __half g_Wk[DMODEL * DMODEL];
__device__ __align__(16) __half g_Wv[DMODEL * DMODEL];
__device__ __align__(16) __half g_Wo[DMODEL * DMODEL];
// Q (pre-scaled, split) and K (plain): [B*H][S][64]. Vt (plain): [B*H][64][S].
__device__ __align__(16) __half g_Qh[TOKENS * DMODEL];
__device__ __align__(16) __half g_Ql[TOKENS * DMODEL];
__device__ __align__(16) __half g_K[TOKENS * DMODEL];
__device__ __align__(16) __half g_Vt[TOKENS * DMODEL];
// O: fp16 split [token][dmodel].
__device__ __align__(16) __half g_Oh[TOKENS * DMODEL];
__device__ __align__(16) __half g_Ol[TOKENS * DMODEL];

__device__ __forceinline__ float neg_inf() { return __int_as_float(0xff800000u); }

__device__ __forceinline__ uint32_t smem_u32(const void* p) {
    uint32_t a;
    asm("{ .reg .u64 t; cvta.to.shared.u64 t, %1; cvt.u32.u64 %0, t; }"
        : "=r"(a) : "l"(p));
    return a;
}

__device__ __forceinline__ uint32_t pack_h2(__half a, __half b) {
    return (uint32_t)__half_as_ushort(a) | ((uint32_t)__half_as_ushort(b) << 16);
}

__device__ __forceinline__ void split_pack_f16(float a, float b,
                                               uint32_t& h, uint32_t& l) {
    __half ha = __float2half_rn(a);
    __half hb = __float2half_rn(b);
    __half la = __float2half_rn(a - __half2float(ha));
    __half lb = __float2half_rn(b - __half2float(hb));
    h = pack_h2(ha, hb);
    l = pack_h2(la, lb);
}

__device__ __forceinline__ void ldsm_x4(uint32_t* r, uint32_t addr) {
    asm volatile("ldmatrix.sync.aligned.m8n8.x4.shared.b16 {%0,%1,%2,%3}, [%4];"
                 : "=r"(r[0]), "=r"(r[1]), "=r"(r[2]), "=r"(r[3]) : "r"(addr));
}

__device__ __forceinline__ void mma16816h(float* d, const uint32_t* a,
                                          const uint32_t* b) {
    asm volatile("mma.sync.aligned.m16n8k16.row.col.f32.f16.f16.f32 "
                 "{%0,%1,%2,%3}, {%4,%5,%6,%7}, {%8,%9}, {%0,%1,%2,%3};"
                 : "+f"(d[0]), "+f"(d[1]), "+f"(d[2]), "+f"(d[3])
                 : "r"(a[0]), "r"(a[1]), "r"(a[2]), "r"(a[3]),
                   "r"(b[0]), "r"(b[1]));
}

__device__ __forceinline__ void cp16(uint32_t saddr, const void* gaddr) {
    asm volatile("cp.async.cg.shared.global [%0], [%1], 16;"
                 :: "r"(saddr), "l"(gaddr));
}

__device__ __forceinline__ void cp_commit() {
    asm volatile("cp.async.commit_group;" ::: "memory");
}
__device__ __forceinline__ void cp_wait1() {
    asm volatile("cp.async.wait_group 1;" ::: "memory");
}
__device__ __forceinline__ void cp_wait0() {
    asm volatile("cp.async.wait_group 0;" ::: "memory");
}

// Full-row swizzle for 128B rows.
__device__ __forceinline__ uint32_t fl_off(int r, int c) {
    return (uint32_t)(r * 128 + ((c ^ (r & 7)) << 4));
}

// ---------------------------------------------------------------------------
// Pre-pass: X -> fp16 hi/lo; weights -> plain fp16.
// ---------------------------------------------------------------------------

__global__ void convert_split(const float* __restrict__ x,
                              const float* __restrict__ Wq,
                              const float* __restrict__ Wk,
                              const float* __restrict__ Wv,
                              const float* __restrict__ Wo)
{
    int i = (blockIdx.x * blockDim.x + threadIdx.x) * 4;
    if (blockIdx.y == 0) {
        if (i >= TOKENS * DMODEL) return;
        float4 v = *(const float4*)(x + i);
        uint32_t h0, h1, l0, l1;
        split_pack_f16(v.x, v.y, h0, l0);
        split_pack_f16(v.z, v.w, h1, l1);
        *(uint2*)(g_Xh + i) = make_uint2(h0, h1);
        *(uint2*)(g_Xl + i) = make_uint2(l0, l1);
    } else {
        if (i >= DMODEL * DMODEL) return;
        const float* src = (blockIdx.y == 1) ? Wq :
                           (blockIdx.y == 2) ? Wk :
                           (blockIdx.y == 3) ? Wv : Wo;
        __half* dst = (blockIdx.y == 1) ? g_Wq :
                      (blockIdx.y == 2) ? g_Wk :
                      (blockIdx.y == 3) ? g_Wv : g_Wo;
        float4 v = *(const float4*)(src + i);
        uint32_t h0 = pack_h2(__float2half_rn(v.x), __float2half_rn(v.y));
        uint32_t h1 = pack_h2(__float2half_rn(v.z), __float2half_rn(v.w));
        *(uint2*)(dst + i) = make_uint2(h0, h1);
    }
}

// ---------------------------------------------------------------------------
// fp16 2-MMA HMMA GEMM (unchanged from r15, passing): CTA 128x128, BK=64,
// 2-stage, 2 CTAs/SM, warp tile 64x32. Stage: Ah 16KB | Al 16KB | B 16KB.
// Safety: trailing __syncthreads after compute protects ISSUE(ch+1) at the
// top of the next iteration (writes stage (ch+1)&1, last read at ch-1).
// ---------------------------------------------------------------------------

#define G_STAGE 49152
#define GEMM_SMEM_BYTES (2 * G_STAGE)

__global__ __launch_bounds__(256, 2) void gemm_f16(float* __restrict__ Cout,
                                                   int qkv_mode)
{
    extern __shared__ char sm[];
    const uint32_t sb = smem_u32(sm);
    const int tid = threadIdx.x;
    const int lane = tid & 31;
    const int wid = tid >> 5;
    const int warp_m = wid >> 2;
    const int warp_n = wid & 3;
    const int z = blockIdx.z;

    const __half *Ah, *Al, *Bp;
    if (qkv_mode) {
        Ah = g_Xh; Al = g_Xl;
        Bp = (z == 0) ? g_Wq : (z == 1 ? g_Wk : g_Wv);
    } else {
        Ah = g_Oh; Al = g_Ol; Bp = g_Wo;
    }
    const int m0 = blockIdx.y * 128;
    const int n0 = blockIdx.x * 128;
    const __half* Agh = Ah + (size_t)m0 * DMODEL;
    const __half* Agl = Al + (size_t)m0 * DMODEL;
    const __half* Bg  = Bp + (size_t)n0 * DMODEL;

    int rT[4]; uint32_t oT[4];
#pragma unroll
    for (int u = 0; u < 4; u++) {
        int lin = u * 256 + tid;
        rT[u] = lin >> 3;
        oT[u] = fl_off(rT[u], lin & 7);
    }
    const int cThis = (tid & 7) * 8;

    float acc[4][4][4];
#pragma unroll
    for (int i = 0; i < 4; i++)
#pragma unroll
        for (int j = 0; j < 4; j++)
#pragma unroll
            for (int u = 0; u < 4; u++) acc[i][j][u] = 0.f;

    const int a_mat = lane >> 3;
    const int a_khalf = a_mat >> 1;
    int rowA[4];
#pragma unroll
    for (int im = 0; im < 4; im++)
        rowA[im] = warp_m * 64 + im * 16 + (a_mat & 1) * 8 + (lane & 7);
    const int b_row4 = ((lane >> 4) << 3) + (lane & 7);
    const int b_chunk4 = (lane >> 3) & 1;

#define ISSUE(chv)                                                                 \
    do {                                                                           \
        const int _k0 = (chv) * 64;                                                \
        const uint32_t _bs = sb + (uint32_t)(((chv) & 1) * G_STAGE);               \
        cp16(_bs + oT[0],          Agh + (size_t)rT[0] * DMODEL + _k0 + cThis);    \
        cp16(_bs + oT[1],          Agh + (size_t)rT[1] * DMODEL + _k0 + cThis);    \
        cp16(_bs + oT[2],          Agh + (size_t)rT[2] * DMODEL + _k0 + cThis);    \
        cp16(_bs + oT[3],          Agh + (size_t)rT[3] * DMODEL + _k0 + cThis);    \
        cp16(_bs + 16384 + oT[0],  Agl + (size_t)rT[0] * DMODEL + _k0 + cThis);    \
        cp16(_bs + 16384 + oT[1],  Agl + (size_t)rT[1] * DMODEL + _k0 + cThis);    \
        cp16(_bs + 16384 + oT[2],  Agl + (size_t)rT[2] * DMODEL + _k0 + cThis);    \
        cp16(_bs + 16384 + oT[3],  Agl + (size_t)rT[3] * DMODEL + _k0 + cThis);    \
        cp16(_bs + 32768 + oT[0],  Bg + (size_t)rT[0] * DMODEL + _k0 + cThis);     \
        cp16(_bs + 32768 + oT[1],  Bg + (size_t)rT[1] * DMODEL + _k0 + cThis);     \
        cp16(_bs + 32768 + oT[2],  Bg + (size_t)rT[2] * DMODEL + _k0 + cThis);     \
        cp16(_bs + 32768 + oT[3],  Bg + (size_t)rT[3] * DMODEL + _k0 + cThis);     \
        cp_commit();                                                               \
    } while (0)

    ISSUE(0);

    for (int ch = 0; ch < 16; ch++) {
        if (ch + 1 < 16) {
            ISSUE(ch + 1);
            cp_wait1();
        } else {
            cp_wait0();
        }
        __syncthreads();

        const uint32_t bs = sb + (uint32_t)((ch & 1) * G_STAGE);
        const uint32_t sAh = bs, sAl = bs + 16384;
        const uint32_t sB = bs + 32768;
#pragma unroll
        for (int kk = 0; kk < 4; kk++) {
            uint32_t ah[4][4], al[4][4];
#pragma unroll
            for (int im = 0; im < 4; im++) {
                uint32_t off = fl_off(rowA[im], kk * 2 + a_khalf);
                ldsm_x4(ah[im], sAh + off);
                ldsm_x4(al[im], sAl + off);
            }
#pragma unroll
            for (int inp = 0; inp < 2; inp++) {
                uint32_t b4[4];
                uint32_t off = fl_off(warp_n * 32 + inp * 16 + b_row4,
                                      kk * 2 + b_chunk4);
                ldsm_x4(b4, sB + off);
#pragma unroll
                for (int im = 0; im < 4; im++) {
                    mma16816h(acc[im][2 * inp], ah[im], b4);
                    mma16816h(acc[im][2 * inp], al[im], b4);
                    mma16816h(acc[im][2 * inp + 1], ah[im], b4 + 2);
                    mma16816h(acc[im][2 * inp + 1], al[im], b4 + 2);
                }
            }
        }
        __syncthreads();
    }
#undef ISSUE

    const int gid = lane >> 2;
    const int tig = lane & 3;
    if (qkv_mode) {
        if (z == 0) {
#pragma unroll
            for (int im = 0; im < 4; im++) {
#pragma unroll
                for (int in = 0; in < 4; in++) {
                    int row = m0 + warp_m * 64 + im * 16 + gid;
                    int col = n0 + warp_n * 32 + in * 8 + tig * 2;
                    int h = col >> 6, hd = col & 63;
#pragma unroll
                    for (int half = 0; half < 2; half++) {
                        int rr = row + half * 8;
                        int bb = rr >> 11, s = rr & 2047;
                        size_t off = (((size_t)(bb * NHEADS + h) * SEQ + s) << 6) + hd;
                        uint32_t hh, ll;
                        split_pack_f16(acc[im][in][half * 2] * 0.125f,
                                       acc[im][in][half * 2 + 1] * 0.125f, hh, ll);
                        *(uint32_t*)(g_Qh + off) = hh;
                        *(uint32_t*)(g_Ql + off) = ll;
                    }
                }
            }
        } else if (z == 1) {
#pragma unroll
            for (int im = 0; im < 4; im++) {
#pragma unroll
                for (int in = 0; in < 4; in++) {
                    int row = m0 + warp_m * 64 + im * 16 + gid;
                    int col = n0 + warp_n * 32 + in * 8 + tig * 2;
                    int h = col >> 6, hd = col & 63;
#pragma unroll
                    for (int half = 0; half < 2; half++) {
                        int rr = row + half * 8;
                        int bb = rr >> 11, s = rr & 2047;
                        size_t off = (((size_t)(bb * NHEADS + h) * SEQ + s) << 6) + hd;
                        *(uint32_t*)(g_K + off) =
                            pack_h2(__float2half_rn(acc[im][in][half * 2]),
                                    __float2half_rn(acc[im][in][half * 2 + 1]));
                    }
                }
            }
        } else {
#pragma unroll
            for (int im = 0; im < 4; im++) {
#pragma unroll
                for (int in = 0; in < 4; in++) {
                    int row = m0 + warp_m * 64 + im * 16 + gid;
                    int col = n0 + warp_n * 32 + in * 8 + tig * 2;
                    int h = col >> 6, hd = col & 63;
#pragma unroll
                    for (int half = 0; half < 2; half++) {
                        int rr = row + half * 8;
                        int bb = rr >> 11, s = rr & 2047;
                        size_t base = ((size_t)(bb * NHEADS + h) * 64 + hd) * SEQ + s;
                        g_Vt[base]       = __float2half_rn(acc[im][in][half * 2]);
                        g_Vt[base + SEQ] = __float2half_rn(acc[im][in][half * 2 + 1]);
                    }
                }
            }
        }
    } else {
#pragma unroll
        for (int im = 0; im < 4; im++) {
#pragma unroll
            for (int in = 0; in < 4; in++) {
                int row = m0 + warp_m * 64 + im * 16 + gid;
                int col = n0 + warp_n * 32 + in * 8 + tig * 2;
#pragma unroll
                for (int half = 0; half < 2; half++) {
                    int rr = row + half * 8;
                    float* dst = Cout + (size_t)rr * DMODEL + col;
                    dst[0] = acc[im][in][half * 2 + 0];
                    dst[1] = acc[im][in][half * 2 + 1];
                }
            }
        }
    }
}

// ---------------------------------------------------------------------------
// Flash attention (causal), fp16. Br=128, Bc=64, 8 warps, 2 CTAs/SM.
// Q split fp16; K, Vt, P plain fp16. 96 MMAs/warp/chunk. 2-stage pipeline.
// RACE-FIXED ordering: wait -> syncthreads -> issue(t+1) -> compute.
//   issue(t+1) writes stage (t+1)&1 = (t-1)&1; the barrier guarantees all
//   warps finished iteration t-1's reads of that stage (r14-validated shape).
// Smem: Q 32KB | 2 stages x 16KB = 64KB -> 128KB/SM at occ 2.
// ---------------------------------------------------------------------------

#define F_SMEM_BYTES (32768 + 2 * 16384)

__global__ __launch_bounds__(256, 2) void flash_mma()
{
    extern __shared__ char sm[];
    const uint32_t sb = smem_u32(sm);
    const int tid = threadIdx.x;
    const int lane = tid & 31;
    const int wq = tid >> 5;
    const int qt = gridDim.x - 1 - blockIdx.x;   // longest first
    const int bh = blockIdx.y;
    const int q0 = qt * 128;
    const int T = 2 * qt + 2;

    const __half* qbh = g_Qh + (size_t)(bh * SEQ + q0) * 64;
    const __half* qbl = g_Ql + (size_t)(bh * SEQ + q0) * 64;
    const __half* kbp = g_K + (size_t)bh * SEQ * 64;
    const __half* vtp = g_Vt + (size_t)bh * 64 * SEQ;

    const uint32_t aQh = sb, aQl = sb + 16384;

#pragma unroll
    for (int u = 0; u < 4; u++) {
        int lin = u * 256 + tid;
        int r = lin >> 3, c = lin & 7;
        uint32_t off = fl_off(r, c);
        *(uint4*)(sm + off)         = *(const uint4*)(qbh + r * 64 + c * 8);
        *(uint4*)(sm + 16384 + off) = *(const uint4*)(qbl + r * 64 + c * 8);
    }

    int rF[2]; uint32_t oF[2];
#pragma unroll
    for (int u = 0; u < 2; u++) {
        int lin = u * 256 + tid;
        rF[u] = lin >> 3;
        oF[u] = fl_off(rF[u], lin & 7);
    }
    const int cF0 = (tid & 7) * 8, cF1 = ((256 + tid) & 7) * 8;

#define F_ISSUE(tt)                                                                \
    do {                                                                           \
        const uint32_t _bs = sb + 32768u + (uint32_t)(((tt) & 1) * 16384);         \
        cp16(_bs + oF[0],        kbp + (size_t)((tt) * 64 + rF[0]) * 64 + cF0);    \
        cp16(_bs + oF[1],        kbp + (size_t)((tt) * 64 + rF[1]) * 64 + cF1);    \
        cp16(_bs + 8192 + oF[0], vtp + (size_t)rF[0] * SEQ + (tt) * 64 + cF0);     \
        cp16(_bs + 8192 + oF[1], vtp + (size_t)rF[1] * SEQ + (tt) * 64 + cF1);     \
        cp_commit();                                                               \
    } while (0)

    F_ISSUE(0);

    const int a_mat = lane >> 3;
    const int a_khalf = a_mat >> 1;
    const int rowA = wq * 16 + (a_mat & 1) * 8 + (lane & 7);
    const int b_row4 = ((lane >> 4) << 3) + (lane & 7);
    const int b_chunk4 = (lane >> 3) & 1;
    const int gid = lane >> 2;
    const int tig = lane & 3;

    float m[2], l[2], o[8][4], s[8][4];
#pragma unroll
    for (int i = 0; i < 2; i++) { m[i] = neg_inf(); l[i] = 0.f; }
#pragma unroll
    for (int j = 0; j < 8; j++)
#pragma unroll
        for (int u = 0; u < 4; u++) o[j][u] = 0.f;

    for (int t = 0; t < T; t++) {
        cp_wait0();        // stage t data ready (only group t in flight here)
        __syncthreads();   // all warps done with stage t-1 compute (+ Q fill)
        if (t + 1 < T) F_ISSUE(t + 1);   // writes stage (t-1)&1 — quiescent

        const uint32_t bs = sb + 32768u + (uint32_t)((t & 1) * 16384);
        const uint32_t aK = bs, aV = bs + 8192;

        // ---- S = Q K^T (split Q, 4 MMAs/jp) ----
#pragma unroll
        for (int j = 0; j < 8; j++)
#pragma unroll
            for (int u = 0; u < 4; u++) s[j][u] = 0.f;

#pragma unroll
        for (int kk = 0; kk < 4; kk++) {
            uint32_t qh4[4], ql4[4];
            uint32_t offa = fl_off(rowA, kk * 2 + a_khalf);
            ldsm_x4(qh4, aQh + offa);
            ldsm_x4(ql4, aQl + offa);
#pragma unroll
            for (int jp = 0; jp < 4; jp++) {
                uint32_t b4[4];
                uint32_t offb = fl_off(jp * 16 + b_row4, kk * 2 + b_chunk4);
                ldsm_x4(b4, aK + offb);
                mma16816h(s[2 * jp], qh4, b4);
                mma16816h(s[2 * jp], ql4, b4);
                mma16816h(s[2 * jp + 1], qh4, b4 + 2);
                mma16816h(s[2 * jp + 1], ql4, b4 + 2);
            }
        }

        if (t >= 2 * qt) {
#pragma unroll
            for (int j = 0; j < 8; j++) {
#pragma unroll
                for (int u = 0; u < 4; u++) {
                    int row = q0 + wq * 16 + (u >> 1) * 8 + gid;
                    int col = t * 64 + j * 8 + tig * 2 + (u & 1);
                    if (col > row) s[j][u] = neg_inf();
                }
            }
        }

        // ---- Online softmax ----
#pragma unroll
        for (int i = 0; i < 2; i++) {
            float mx = neg_inf();
#pragma unroll
            for (int j = 0; j < 8; j++) {
                mx = fmaxf(mx, s[j][i * 2]);
                mx = fmaxf(mx, s[j][i * 2 + 1]);
            }
            mx = fmaxf(mx, __shfl_xor_sync(0xffffffffu, mx, 1));
            mx = fmaxf(mx, __shfl_xor_sync(0xffffffffu, mx, 2));
            float mnew = fmaxf(m[i], mx);
            float corr = __expf(m[i] - mnew);
            float rs = 0.f;
#pragma unroll
            for (int j = 0; j < 8; j++) {
                float e0 = __expf(s[j][i * 2] - mnew);
                float e1 = __expf(s[j][i * 2 + 1] - mnew);
                s[j][i * 2] = e0;
                s[j][i * 2 + 1] = e1;
                rs += e0 + e1;
            }
            rs += __shfl_xor_sync(0xffffffffu, rs, 1);
            rs += __shfl_xor_sync(0xffffffffu, rs, 2);
            l[i] = l[i] * corr + rs;
            m[i] = mnew;
#pragma unroll
            for (int j = 0; j < 8; j++) {
                o[j][i * 2] *= corr;
                o[j][i * 2 + 1] *= corr;
            }
        }

        // ---- O += P Vt (P plain fp16, 2 MMAs/jp) ----
#pragma unroll
        for (int kk = 0; kk < 4; kk++) {
            uint32_t ph[4];
#pragma unroll
            for (int half = 0; half < 2; half++) {
                const float* sv = s[2 * kk + half];
                ph[half * 2]     = pack_h2(__float2half_rn(sv[0]),
                                           __float2half_rn(sv[1]));
                ph[half * 2 + 1] = pack_h2(__float2half_rn(sv[2]),
                                           __float2half_rn(sv[3]));
            }
#pragma unroll
            for (int jp = 0; jp < 4; jp++) {
                uint32_t v4[4];
                uint32_t offv = fl_off(jp * 16 + b_row4, kk * 2 + b_chunk4);
                ldsm_x4(v4, aV + offv);
                mma16816h(o[2 * jp], ph, v4);
                mma16816h(o[2 * jp + 1], ph, v4 + 2);
            }
        }
    }
#undef F_ISSUE

    // ---- Epilogue: normalize, write fp16 split O [token][dmodel] ----
    const int bb = bh >> 4;
    const int h = bh & 15;
    float inv0 = 1.f / l[0];
    float inv1 = 1.f / l[1];
#pragma unroll
    for (int j = 0; j < 8; j++) {
        int col = h * 64 + j * 8 + tig * 2;
        int r0 = q0 + wq * 16 + gid;
        size_t off0 = (size_t)(bb * SEQ + r0) * DMODEL + col;
        size_t off1 = (size_t)(bb * SEQ + r0 + 8) * DMODEL + col;
        uint32_t hh, ll;
        split_pack_f16(o[j][0] * inv0, o[j][1] * inv0, hh, ll);
        *(uint32_t*)(g_Oh + off0) = hh;
        *(uint32_t*)(g_Ol + off0) = ll;
        split_pack_f16(o[j][2] * inv1, o[j][3] * inv1, hh, ll);
        *(uint32_t*)(g_Oh + off1) = hh;
        *(uint32_t*)(g_Ol + off1) = ll;
    }
}

// ---------------------------------------------------------------------------

extern "C" void kernel_launch(void* const* d_in, const int* in_sizes, int n_in,
                              void* d_out, int out_size)
{
    (void)in_sizes; (void)n_in; (void)out_size;
    const float* x  = (const float*)d_in[0];
    const float* Wq = (const float*)d_in[1];
    const float* Wk = (const float*)d_in[2];
    const float* Wv = (const float*)d_in[3];
    const float* Wo = (const float*)d_in[4];
    float* out = (float*)d_out;

    cudaFuncSetAttribute(gemm_f16, cudaFuncAttributeMaxDynamicSharedMemorySize,
                         GEMM_SMEM_BYTES);
    cudaFuncSetAttribute(flash_mma, cudaFuncAttributeMaxDynamicSharedMemorySize,
                         F_SMEM_BYTES);

    convert_split<<<dim3(4096, 5), 256>>>(x, Wq, Wk, Wv, Wo);

    dim3 gqkv(DMODEL / 128, TOKENS / 128, 3);   // (8, 32, 3)
    gemm_f16<<<gqkv, 256, GEMM_SMEM_BYTES>>>(nullptr, 1);

    dim3 gatt(SEQ / 128, 2 * NHEADS);           // (16, 32)
    flash_mma<<<gatt, 256, F_SMEM_BYTES>>>();

    dim3 gout(DMODEL / 128, TOKENS / 128, 1);   // (8, 32)
    gemm_f16<<<gout, 256, GEMM_SMEM_BYTES>>>(out, 0);
}